// round 2
// baseline (speedup 1.0000x reference)
#include <cuda_runtime.h>
#include <math.h>

// Problem constants
#define BB 16
#define NN 1024
#define DD 512
#define ROWS (BB*NN)          // 16384
#define TIME_STEP 3

typedef unsigned long long u64;

// ---------------- scratch (device globals, no allocation) ----------------
__device__ float g_nodes[BB*NN*DD];         // 33.5 MB
__device__ float g_ain  [BB*NN*DD];         // reused as rv*f after gates
__device__ float g_aout [BB*NN*DD];         // reused as t after gates
__device__ float g_gates[BB*NN*3*DD];       // [16384][1536]: g3|g4|g5
__device__ float g_u3   [BB*NN*DD];         // reused as zv after elem1
__device__ float g_wT   [2*DD*3*DD];        // [1024][1536] = [w3w^T|w4w^T|w5w^T]
__device__ float g_w3uT [DD*DD];            // [512][512]
__device__ float g_w5uT [DD*DD];

// ---------------- f32x2 helpers (sm_103a packed fp32) ----------------
__device__ __forceinline__ u64 pk2(float x, float y) {
    u64 r;
    unsigned xi = __float_as_uint(x), yi = __float_as_uint(y);
    asm("mov.b64 %0, {%1, %2};" : "=l"(r) : "r"(xi), "r"(yi));
    return r;
}
__device__ __forceinline__ void upk2(u64 v, float& x, float& y) {
    unsigned xi, yi;
    asm("mov.b64 {%0, %1}, %2;" : "=r"(xi), "=r"(yi) : "l"(v));
    x = __uint_as_float(xi); y = __uint_as_float(yi);
}
__device__ __forceinline__ void fma2(u64& c, u64 a, u64 b) {
    asm("fma.rn.f32x2 %0, %1, %2, %0;" : "+l"(c) : "l"(a), "l"(b));
}

// ---------------- generic 128x128 tiled fp32 GEMM ----------------
// C[m,n] = sum_k A'[m,k] * B[k,n]   (all row-major)
// A' = A for k < ksplit, else A2 at (k - ksplit). Both share lda.
// blockIdx.z batches: A += z*aB, B += z*bB, C += z*cB. Grid must tile exactly
// (M%128==0, N%128==0, K%16==0).
#define BKT 16
#define SMPAD 132   // 128 + 4 pad: keeps 16B alignment, reduces bank conflicts

__global__ __launch_bounds__(256, 2)
void gemm_f32(const float* __restrict__ A, const float* __restrict__ A2, int ksplit,
              int lda,
              const float* __restrict__ Bm, int ldb,
              float* __restrict__ C, int ldc,
              int Kd, long aB, long bB, long cB)
{
    A  += (long)blockIdx.z * aB;
    A2 += (long)blockIdx.z * aB;
    Bm += (long)blockIdx.z * bB;
    C  += (long)blockIdx.z * cB;

    __shared__ float As[2][BKT][SMPAD];
    __shared__ float Bs[2][BKT][SMPAD];

    const int tid  = threadIdx.x;
    const int tx   = tid & 15;        // 0..15  (n direction)
    const int ty   = tid >> 4;        // 0..15  (m direction)
    const int m0   = blockIdx.y * 128;
    const int n0   = blockIdx.x * 128;

    // A-tile loader mapping: 128x16 tile, 8 floats/thread (2x float4)
    const int arow = tid >> 2;        // 0..63
    const int acol = tid & 3;         // 0..3  -> cols acol*4..+3
    // B-tile loader mapping: 16x128 tile
    const int brow = tid >> 5;        // 0..7
    const int bcol = tid & 31;        // 0..31 -> cols bcol*4..+3

    u64 c2[8][4];
    #pragma unroll
    for (int i = 0; i < 8; i++)
        #pragma unroll
        for (int j = 0; j < 4; j++) c2[i][j] = 0ULL;

    const int KT = Kd / BKT;

    // ---- prologue: load tile 0 into buffer 0 ----
    {
        int k0 = 0;
        const float* src = A;
        int kk0 = k0;
        if (kk0 >= ksplit) { src = A2; kk0 -= ksplit; }
        float4 ra0 = *(const float4*)&src[(long)(m0 + arow) * lda + kk0 + acol*4];
        float4 ra1 = *(const float4*)&src[(long)(m0 + arow + 64) * lda + kk0 + acol*4];
        float4 rb0 = *(const float4*)&Bm[(long)(k0 + brow) * ldb + n0 + bcol*4];
        float4 rb1 = *(const float4*)&Bm[(long)(k0 + brow + 8) * ldb + n0 + bcol*4];
        As[0][acol*4+0][arow] = ra0.x; As[0][acol*4+1][arow] = ra0.y;
        As[0][acol*4+2][arow] = ra0.z; As[0][acol*4+3][arow] = ra0.w;
        As[0][acol*4+0][arow+64] = ra1.x; As[0][acol*4+1][arow+64] = ra1.y;
        As[0][acol*4+2][arow+64] = ra1.z; As[0][acol*4+3][arow+64] = ra1.w;
        *(float4*)&Bs[0][brow][bcol*4]   = rb0;
        *(float4*)&Bs[0][brow+8][bcol*4] = rb1;
    }
    __syncthreads();

    for (int kt = 0; kt < KT; kt++) {
        const int cur = kt & 1;
        float4 ra0, ra1, rb0, rb1;
        const bool more = (kt + 1 < KT);
        if (more) {
            int k0 = (kt + 1) * BKT;
            const float* src = A;
            int kk0 = k0;
            if (kk0 >= ksplit) { src = A2; kk0 -= ksplit; }
            ra0 = *(const float4*)&src[(long)(m0 + arow) * lda + kk0 + acol*4];
            ra1 = *(const float4*)&src[(long)(m0 + arow + 64) * lda + kk0 + acol*4];
            rb0 = *(const float4*)&Bm[(long)(k0 + brow) * ldb + n0 + bcol*4];
            rb1 = *(const float4*)&Bm[(long)(k0 + brow + 8) * ldb + n0 + bcol*4];
        }

        // ---- compute current tile ----
        #pragma unroll
        for (int kk = 0; kk < BKT; kk++) {
            float4 av0 = *(const float4*)&As[cur][kk][ty*4];
            float4 av1 = *(const float4*)&As[cur][kk][64 + ty*4];
            float4 bv0 = *(const float4*)&Bs[cur][kk][tx*4];
            float4 bv1 = *(const float4*)&Bs[cur][kk][64 + tx*4];
            u64 b2[4];
            b2[0] = pk2(bv0.x, bv0.y); b2[1] = pk2(bv0.z, bv0.w);
            b2[2] = pk2(bv1.x, bv1.y); b2[3] = pk2(bv1.z, bv1.w);
            float aa[8] = {av0.x, av0.y, av0.z, av0.w, av1.x, av1.y, av1.z, av1.w};
            #pragma unroll
            for (int i = 0; i < 8; i++) {
                u64 a2 = pk2(aa[i], aa[i]);
                #pragma unroll
                for (int j = 0; j < 4; j++) fma2(c2[i][j], a2, b2[j]);
            }
        }

        if (more) {
            const int nb = cur ^ 1;
            As[nb][acol*4+0][arow] = ra0.x; As[nb][acol*4+1][arow] = ra0.y;
            As[nb][acol*4+2][arow] = ra0.z; As[nb][acol*4+3][arow] = ra0.w;
            As[nb][acol*4+0][arow+64] = ra1.x; As[nb][acol*4+1][arow+64] = ra1.y;
            As[nb][acol*4+2][arow+64] = ra1.z; As[nb][acol*4+3][arow+64] = ra1.w;
            *(float4*)&Bs[nb][brow][bcol*4]   = rb0;
            *(float4*)&Bs[nb][brow+8][bcol*4] = rb1;
        }
        __syncthreads();
    }

    // ---- epilogue ----
    #pragma unroll
    for (int i = 0; i < 8; i++) {
        int r = m0 + ((i < 4) ? (ty*4 + i) : (64 + ty*4 + (i - 4)));
        float4 v;
        upk2(c2[i][0], v.x, v.y); upk2(c2[i][1], v.z, v.w);
        *(float4*)&C[(long)r * ldc + n0 + tx*4] = v;
        upk2(c2[i][2], v.x, v.y); upk2(c2[i][3], v.z, v.w);
        *(float4*)&C[(long)r * ldc + n0 + 64 + tx*4] = v;
    }
}

// ---------------- weight transpose (once per launch) ----------------
__global__ void prep_weights(const float* __restrict__ w3w, const float* __restrict__ w4w,
                             const float* __restrict__ w5w, const float* __restrict__ w3u,
                             const float* __restrict__ w5u)
{
    int idx = blockIdx.x * blockDim.x + threadIdx.x;
    if (idx < 1024 * 1536) {
        int k = idx / 1536, col = idx - k * 1536;
        int j = col >> 9, e = col & 511;
        const float* w = (j == 0) ? w3w : ((j == 1) ? w4w : w5w);
        g_wT[idx] = w[e * 1024 + k];
    }
    if (idx < 512 * 512) {
        int k = idx >> 9, e = idx & 511;
        g_w3uT[idx] = w3u[e * 512 + k];
        g_w5uT[idx] = w5u[e * 512 + k];
    }
}

// ---------------- elementwise ----------------
__global__ void elem1(const float* __restrict__ b3w, const float* __restrict__ b3u,
                      const float* __restrict__ b4w)
{
    int i = blockIdx.x * blockDim.x + threadIdx.x;   // ROWS*DD threads
    int row = i >> 9, e = i & 511;
    float u  = g_u3[i] + b3u[e];
    float f  = g_nodes[i];
    float g3 = g_gates[(long)row * 1536 + e];
    float g4 = g_gates[(long)row * 1536 + 512 + e];
    float z  = 1.f / (1.f + expf(-(g3 + b3w[e] + u)));
    float r  = 1.f / (1.f + expf(-(g4 + b4w[e] + u)));
    g_u3[i]  = z;        // zv (overwrites u3)
    g_ain[i] = r * f;    // rv*f (overwrites a_in)
}

__global__ void elem2(const float* __restrict__ b5w, const float* __restrict__ b5u)
{
    int i = blockIdx.x * blockDim.x + threadIdx.x;
    int row = i >> 9, e = i & 511;
    float t  = g_aout[i];                              // (rv*f) @ w5u^T
    float g5 = g_gates[(long)row * 1536 + 1024 + e];
    float hv = tanhf(g5 + b5w[e] + t + b5u[e]);
    float z  = g_u3[i];
    float f  = g_nodes[i];
    g_nodes[i] = (1.f - z) * f + z * hv;
}

// ---------------- vectorized copy ----------------
__global__ void copy4(const float4* __restrict__ src, float4* __restrict__ dst, int n4)
{
    int i = blockIdx.x * blockDim.x + threadIdx.x;
    if (i < n4) dst[i] = src[i];
}

// ---------------- host launcher ----------------
extern "C" void kernel_launch(void* const* d_in, const int* in_sizes, int n_in,
                              void* d_out, int out_size)
{
    (void)in_sizes; (void)n_in; (void)out_size;
    const float* x     = (const float*)d_in[0];
    const float* in_m  = (const float*)d_in[1];
    const float* out_m = (const float*)d_in[2];
    const float* w3w   = (const float*)d_in[3];
    const float* b3w   = (const float*)d_in[4];
    const float* w3u   = (const float*)d_in[5];
    const float* b3u   = (const float*)d_in[6];
    const float* w4w   = (const float*)d_in[7];
    const float* b4w   = (const float*)d_in[8];
    const float* w5w   = (const float*)d_in[9];
    const float* b5w   = (const float*)d_in[10];
    const float* w5u   = (const float*)d_in[11];
    const float* b5u   = (const float*)d_in[12];
    float* out = (float*)d_out;

    float *nodes, *ain, *aout, *gates, *u3, *wT, *w3uT, *w5uT;
    cudaGetSymbolAddress((void**)&nodes, g_nodes);
    cudaGetSymbolAddress((void**)&ain,   g_ain);
    cudaGetSymbolAddress((void**)&aout,  g_aout);
    cudaGetSymbolAddress((void**)&gates, g_gates);
    cudaGetSymbolAddress((void**)&u3,    g_u3);
    cudaGetSymbolAddress((void**)&wT,    g_wT);
    cudaGetSymbolAddress((void**)&w3uT,  g_w3uT);
    cudaGetSymbolAddress((void**)&w5uT,  g_w5uT);

    const long ND = (long)NN * DD;          // 524288
    const int  BIG = 1 << 30;               // "no split"

    // init: nodes = x
    copy4<<<(BB*NN*DD/4 + 255)/256, 256>>>((const float4*)x, (float4*)nodes, BB*NN*DD/4);
    // transpose weights
    prep_weights<<<(1024*1536 + 255)/256, 256>>>(w3w, w4w, w5w, w3u, w5u);

    for (int step = 0; step < TIME_STEP; step++) {
        // a_in = in_matrix @ nodes   (per batch)   M=1024 N=512 K=1024
        dim3 gprop(512/128, 1024/128, BB);
        gemm_f32<<<gprop, 256>>>(in_m, in_m, BIG, 1024, nodes, 512, ain, 512,
                                 1024, 0L, ND, ND);
        gemm_f32<<<gprop, 256>>>(out_m, out_m, BIG, 1024, nodes, 512, aout, 512,
                                 1024, 0L, ND, ND);

        // gates = [a_in|a_out] @ wT   M=16384 N=1536 K=1024 (split A at k=512)
        dim3 ggate(1536/128, ROWS/128, 1);
        gemm_f32<<<ggate, 256>>>(ain, aout, 512, 512, wT, 1536, gates, 1536,
                                 1024, 0L, 0L, 0L);

        // u3 = nodes @ w3u^T   M=16384 N=512 K=512
        dim3 gu(512/128, ROWS/128, 1);
        gemm_f32<<<gu, 256>>>(nodes, nodes, BIG, 512, w3uT, 512, u3, 512,
                              512, 0L, 0L, 0L);

        // zv, rv*f
        elem1<<<ROWS*DD/256, 256>>>(b3w, b3u, b4w);

        // t = (rv*f) @ w5u^T  -> into g_aout
        gemm_f32<<<gu, 256>>>(ain, ain, BIG, 512, w5uT, 512, aout, 512,
                              512, 0L, 0L, 0L);

        // hv, nodes update
        elem2<<<ROWS*DD/256, 256>>>(b5w, b5u);
    }

    // output: nodes (B*N*D floats) then in_matrix (N*N floats)
    copy4<<<(BB*NN*DD/4 + 255)/256, 256>>>((const float4*)nodes, (float4*)out, BB*NN*DD/4);
    copy4<<<(NN*NN/4 + 255)/256, 256>>>((const float4*)in_m,
                                        (float4*)(out + (long)BB*NN*DD), NN*NN/4);
}

// round 4
// speedup vs baseline: 1.7278x; 1.7278x over previous
#include <cuda_runtime.h>
#include <cuda_bf16.h>
#include <cstdint>
#include <math.h>

#define BB 16
#define NN 1024
#define DD 512
#define ROWS (BB*NN)          // 16384
#define TIME_STEP 3

// ---------------- fp32 scratch ----------------
__device__ float g_nodes[BB*NN*DD];
__device__ float g_u3   [BB*NN*DD];          // u3, then zv
__device__ float g_t    [BB*NN*DD];          // (rv*f)@w5u^T
__device__ float g_gates[BB*NN*3*DD];        // [16384][1536]

// ---------------- bf16 hi/lo operand buffers ----------------
__device__ __nv_bfloat16 g_inM_h [NN*NN], g_inM_l [NN*NN];
__device__ __nv_bfloat16 g_outM_h[NN*NN], g_outM_l[NN*NN];
__device__ __nv_bfloat16 g_w3w_h[DD*2*DD], g_w3w_l[DD*2*DD];
__device__ __nv_bfloat16 g_w4w_h[DD*2*DD], g_w4w_l[DD*2*DD];
__device__ __nv_bfloat16 g_w5w_h[DD*2*DD], g_w5w_l[DD*2*DD];
__device__ __nv_bfloat16 g_w3u_h[DD*DD],   g_w3u_l[DD*DD];
__device__ __nv_bfloat16 g_w5u_h[DD*DD],   g_w5u_l[DD*DD];
__device__ __nv_bfloat16 g_ndT_h[BB*DD*NN], g_ndT_l[BB*DD*NN];   // [b][d][n]
__device__ __nv_bfloat16 g_ndb_h[BB*NN*DD], g_ndb_l[BB*NN*DD];   // [b][n][d]
__device__ __nv_bfloat16 g_ain_h[BB*NN*DD], g_ain_l[BB*NN*DD];
__device__ __nv_bfloat16 g_aout_h[BB*NN*DD], g_aout_l[BB*NN*DD];
__device__ __nv_bfloat16 g_rf_h [BB*NN*DD], g_rf_l [BB*NN*DD];

// ---------------- helpers ----------------
__device__ __forceinline__ uint32_t smem_u32(const void* p) {
    uint32_t a;
    asm("{ .reg .u64 t; cvta.to.shared.u64 t, %1; cvt.u32.u64 %0, t; }" : "=r"(a) : "l"(p));
    return a;
}
__device__ __forceinline__ void split2(float x, float y, uint32_t& hi, uint32_t& lo) {
    __nv_bfloat162 h = __floats2bfloat162_rn(x, y);   // low=x, high=y
    float rx = x - __bfloat162float(__low2bfloat16(h));
    float ry = y - __bfloat162float(__high2bfloat16(h));
    __nv_bfloat162 l = __floats2bfloat162_rn(rx, ry);
    hi = *(uint32_t*)&h; lo = *(uint32_t*)&l;
}
__device__ __forceinline__ void cpa16(uint32_t s, const void* g) {
    asm volatile("cp.async.cg.shared.global [%0], [%1], 16;" :: "r"(s), "l"(g));
}
__device__ __forceinline__ void cpa_commit() {
    asm volatile("cp.async.commit_group;" ::: "memory");
}
__device__ __forceinline__ void cpa_wait0() {
    asm volatile("cp.async.wait_group 0;" ::: "memory");
}
__device__ __forceinline__ void cpa_wait1() {
    asm volatile("cp.async.wait_group 1;" ::: "memory");
}
__device__ __forceinline__ void ldm_x4(uint32_t* r, uint32_t addr) {
    asm volatile("ldmatrix.sync.aligned.m8n8.x4.shared.b16 {%0,%1,%2,%3}, [%4];"
                 : "=r"(r[0]), "=r"(r[1]), "=r"(r[2]), "=r"(r[3]) : "r"(addr));
}
__device__ __forceinline__ void mma_bf16(float* d, const uint32_t* a, const uint32_t* b) {
    asm volatile("mma.sync.aligned.m16n8k16.row.col.f32.bf16.bf16.f32 "
                 "{%0,%1,%2,%3}, {%4,%5,%6,%7}, {%8,%9}, {%0,%1,%2,%3};"
                 : "+f"(d[0]), "+f"(d[1]), "+f"(d[2]), "+f"(d[3])
                 : "r"(a[0]), "r"(a[1]), "r"(a[2]), "r"(a[3]), "r"(b[0]), "r"(b[1]));
}

// ======================= bf16x3 mma.sync GEMM =======================
// C[m][n] = sum_k A'[m][k]*B[n][k]; A,B already split into bf16 hi/lo, k-major.
// A' = A for k<ksplit else A2 at k-ksplit. blockIdx.z batch via aB/bB/cB/coB.
// Epilogue: fp32 C (if C!=null) and/or bf16 hi/lo (if Coh!=null).
#define KC 32
#define RS 40                      // smem row stride in halves (80B, conflict-free)
#define TILE_HB (128*RS)           // halves per tile
#define STAGE_HB (4*TILE_HB)       // Ahi|Alo|Bhi|Blo
#define GEMM_SMEM (2*STAGE_HB*2)   // 81920 bytes

__device__ __forceinline__ void load_tile(uint32_t sbase, const __nv_bfloat16* g,
                                          int ld, int tid)
{
    int row = tid >> 2, cb = tid & 3;
    cpa16(sbase + (uint32_t)(row*RS + cb*8)*2, g + (long)row*ld + cb*8);
    cpa16(sbase + (uint32_t)((row+64)*RS + cb*8)*2, g + (long)(row+64)*ld + cb*8);
}

__global__ __launch_bounds__(256, 1)
void gemm_mma(const __nv_bfloat16* __restrict__ Ah, const __nv_bfloat16* __restrict__ Al,
              const __nv_bfloat16* __restrict__ A2h, const __nv_bfloat16* __restrict__ A2l,
              int ksplit, int lda,
              const __nv_bfloat16* __restrict__ Bh, const __nv_bfloat16* __restrict__ Bl,
              int ldb,
              float* __restrict__ C, int ldc,
              __nv_bfloat16* __restrict__ Coh, __nv_bfloat16* __restrict__ Col, int ldco,
              int Kd, long aB, long bB, long cB, long coB)
{
    extern __shared__ char smem[];
    const uint32_t sb = smem_u32(smem);

    const long z = blockIdx.z;
    Ah += z*aB; Al += z*aB; A2h += z*aB; A2l += z*aB;
    Bh += z*bB; Bl += z*bB;
    if (C)   C   += z*cB;
    if (Coh) { Coh += z*coB; Col += z*coB; }

    const int tid = threadIdx.x;
    const int wid = tid >> 5, lane = tid & 31;
    const int m0 = blockIdx.y * 128, n0 = blockIdx.x * 128;
    const int wrow = (wid & 1) * 64;      // warp M offset (2)
    const int wcol = (wid >> 1) * 32;     // warp N offset (4)

    float acc[4][4][4];
    #pragma unroll
    for (int i = 0; i < 4; i++)
        #pragma unroll
        for (int j = 0; j < 4; j++)
            #pragma unroll
            for (int k = 0; k < 4; k++) acc[i][j][k] = 0.f;

    const int KT = Kd / KC;

    // stage loader
    auto load_stage = [&](int t) {
        int kbase = t * KC;
        const __nv_bfloat16 *pah = Ah, *pal = Al;
        int ka = kbase;
        if (kbase >= ksplit) { pah = A2h; pal = A2l; ka -= ksplit; }
        uint32_t s = sb + (uint32_t)(t & 1) * STAGE_HB * 2;
        load_tile(s,                pah + (long)m0*lda + ka, lda, tid);
        load_tile(s + TILE_HB*2,    pal + (long)m0*lda + ka, lda, tid);
        load_tile(s + 2*TILE_HB*2,  Bh  + (long)n0*ldb + kbase, ldb, tid);
        load_tile(s + 3*TILE_HB*2,  Bl  + (long)n0*ldb + kbase, ldb, tid);
        cpa_commit();
    };

    load_stage(0);

    for (int t = 0; t < KT; t++) {
        if (t + 1 < KT) { load_stage(t + 1); cpa_wait1(); }
        else            { cpa_wait0(); }
        __syncthreads();

        const uint32_t s = sb + (uint32_t)(t & 1) * STAGE_HB * 2;
        const uint32_t sAh = s, sAl = s + TILE_HB*2;
        const uint32_t sBh = s + 2*TILE_HB*2, sBl = s + 3*TILE_HB*2;

        const int ar = lane & 15, acg = lane >> 4;      // A ldmatrix lanes
        const int bg = lane >> 3, bl8 = lane & 7;       // B ldmatrix lanes

        #pragma unroll
        for (int ks = 0; ks < 2; ks++) {
            uint32_t ah[4][4], al[4][4], bh[2][4], bl[2][4];
            #pragma unroll
            for (int mb = 0; mb < 4; mb++) {
                uint32_t off = (uint32_t)((wrow + mb*16 + ar)*RS + ks*16 + acg*8)*2;
                ldm_x4(ah[mb], sAh + off);
                ldm_x4(al[mb], sAl + off);
            }
            #pragma unroll
            for (int nb2 = 0; nb2 < 2; nb2++) {
                int rowb = wcol + nb2*16 + ((bg >> 1) & 1)*8 + bl8;
                int kcb  = ks*16 + (bg & 1)*8;
                uint32_t off = (uint32_t)(rowb*RS + kcb)*2;
                ldm_x4(bh[nb2], sBh + off);
                ldm_x4(bl[nb2], sBl + off);
            }
            #pragma unroll
            for (int mb = 0; mb < 4; mb++)
                #pragma unroll
                for (int nb = 0; nb < 4; nb++) {
                    const uint32_t* ph = &bh[nb >> 1][(nb & 1)*2];
                    const uint32_t* pl = &bl[nb >> 1][(nb & 1)*2];
                    mma_bf16(acc[mb][nb], ah[mb], ph);
                    mma_bf16(acc[mb][nb], ah[mb], pl);
                    mma_bf16(acc[mb][nb], al[mb], ph);
                }
        }
        __syncthreads();
    }

    // ---- epilogue ----
    const int r0 = lane >> 2, c0 = (lane & 3)*2;
    #pragma unroll
    for (int mb = 0; mb < 4; mb++) {
        #pragma unroll
        for (int nb = 0; nb < 4; nb++) {
            long row = m0 + wrow + mb*16 + r0;
            int  col = n0 + wcol + nb*8 + c0;
            float* a = acc[mb][nb];
            if (C) {
                *(float2*)&C[row*ldc + col]     = make_float2(a[0], a[1]);
                *(float2*)&C[(row+8)*ldc + col] = make_float2(a[2], a[3]);
            }
            if (Coh) {
                uint32_t hi, lo;
                split2(a[0], a[1], hi, lo);
                *(uint32_t*)&Coh[row*ldco + col] = hi;
                *(uint32_t*)&Col[row*ldco + col] = lo;
                split2(a[2], a[3], hi, lo);
                *(uint32_t*)&Coh[(row+8)*ldco + col] = hi;
                *(uint32_t*)&Col[(row+8)*ldco + col] = lo;
            }
        }
    }
}

// ---------------- converters ----------------
__global__ void cvt_mat(const float* __restrict__ src, __nv_bfloat16* __restrict__ hi,
                        __nv_bfloat16* __restrict__ lo, int n)
{
    int i = (blockIdx.x*blockDim.x + threadIdx.x)*2;
    if (i < n) {
        float2 v = *(const float2*)&src[i];
        uint32_t h, l;
        split2(v.x, v.y, h, l);
        *(uint32_t*)&hi[i] = h;
        *(uint32_t*)&lo[i] = l;
    }
}

// nodes [b][n][d] fp32 -> ndb hi/lo (straight) + ndT hi/lo (transposed [b][d][n])
__global__ void transpose_cvt(const float* __restrict__ src)
{
    __shared__ float tile[32][33];
    const int b = blockIdx.z;
    const int d0 = blockIdx.x*32, n0 = blockIdx.y*32;
    const float* s = src + (long)b*NN*DD;
    const int tid = threadIdx.x;
    #pragma unroll
    for (int i = 0; i < 4; i++) {
        int p = tid + i*256, n = p >> 5, d = p & 31;
        tile[n][d] = s[(long)(n0+n)*DD + d0 + d];
    }
    __syncthreads();
    #pragma unroll
    for (int i = 0; i < 2; i++) {
        int p = tid + i*256, n = p >> 4, dp = p & 15;
        uint32_t h, l;
        split2(tile[n][dp*2], tile[n][dp*2+1], h, l);
        long o = ((long)b*NN + n0 + n)*DD + d0 + dp*2;
        *(uint32_t*)&g_ndb_h[o] = h; *(uint32_t*)&g_ndb_l[o] = l;
    }
    #pragma unroll
    for (int i = 0; i < 2; i++) {
        int p = tid + i*256, d = p >> 4, np = p & 15;
        uint32_t h, l;
        split2(tile[np*2][d], tile[np*2+1][d], h, l);
        long o = ((long)b*DD + d0 + d)*NN + n0 + np*2;
        *(uint32_t*)&g_ndT_h[o] = h; *(uint32_t*)&g_ndT_l[o] = l;
    }
}

// ---------------- elementwise ----------------
__global__ void elem1(const float* __restrict__ b3w, const float* __restrict__ b3u,
                      const float* __restrict__ b4w)
{
    int p = blockIdx.x*blockDim.x + threadIdx.x;    // over ROWS*DD/2
    long i = (long)p*2;
    int row = (int)(i >> 9), e = (int)(i & 511);
    float2 u = *(const float2*)&g_u3[i];
    float2 f = *(const float2*)&g_nodes[i];
    float g3a = g_gates[(long)row*1536 + e],       g3b = g_gates[(long)row*1536 + e + 1];
    float g4a = g_gates[(long)row*1536 + 512 + e], g4b = g_gates[(long)row*1536 + 512 + e + 1];
    float ua = u.x + b3u[e], ub = u.y + b3u[e+1];
    float za = 1.f/(1.f + expf(-(g3a + b3w[e] + ua)));
    float zb = 1.f/(1.f + expf(-(g3b + b3w[e+1] + ub)));
    float ra = 1.f/(1.f + expf(-(g4a + b4w[e] + ua)));
    float rb = 1.f/(1.f + expf(-(g4b + b4w[e+1] + ub)));
    *(float2*)&g_u3[i] = make_float2(za, zb);
    uint32_t h, l;
    split2(ra*f.x, rb*f.y, h, l);
    *(uint32_t*)&g_rf_h[i] = h;
    *(uint32_t*)&g_rf_l[i] = l;
}

__global__ void elem2(const float* __restrict__ b5w, const float* __restrict__ b5u)
{
    long i = (long)blockIdx.x*blockDim.x + threadIdx.x;
    int row = (int)(i >> 9), e = (int)(i & 511);
    float t  = g_t[i];
    float g5 = g_gates[(long)row*1536 + 1024 + e];
    float hv = tanhf(g5 + b5w[e] + t + b5u[e]);
    float z  = g_u3[i];
    float f  = g_nodes[i];
    g_nodes[i] = (1.f - z)*f + z*hv;
}

__global__ void copy4(const float4* __restrict__ src, float4* __restrict__ dst, int n4)
{
    int i = blockIdx.x*blockDim.x + threadIdx.x;
    if (i < n4) dst[i] = src[i];
}

// ---------------- host launcher ----------------
extern "C" void kernel_launch(void* const* d_in, const int* in_sizes, int n_in,
                              void* d_out, int out_size)
{
    (void)in_sizes; (void)n_in; (void)out_size;
    const float* x     = (const float*)d_in[0];
    const float* in_m  = (const float*)d_in[1];
    const float* out_m = (const float*)d_in[2];
    const float* w3w   = (const float*)d_in[3];
    const float* b3w   = (const float*)d_in[4];
    const float* w3u   = (const float*)d_in[5];
    const float* b3u   = (const float*)d_in[6];
    const float* w4w   = (const float*)d_in[7];
    const float* b4w   = (const float*)d_in[8];
    const float* w5w   = (const float*)d_in[9];
    const float* b5w   = (const float*)d_in[10];
    const float* w5u   = (const float*)d_in[11];
    const float* b5u   = (const float*)d_in[12];
    float* out = (float*)d_out;

    float *nodes, *u3, *tt, *gates;
    cudaGetSymbolAddress((void**)&nodes, g_nodes);
    cudaGetSymbolAddress((void**)&u3,    g_u3);
    cudaGetSymbolAddress((void**)&tt,    g_t);
    cudaGetSymbolAddress((void**)&gates, g_gates);

    __nv_bfloat16 *inMh,*inMl,*outMh,*outMl,*w3wh,*w3wl,*w4wh,*w4wl,*w5wh,*w5wl;
    __nv_bfloat16 *w3uh,*w3ul,*w5uh,*w5ul,*ndTh,*ndTl,*ndbh,*ndbl;
    __nv_bfloat16 *ainh,*ainl,*aouth,*aoutl,*rfh,*rfl;
    cudaGetSymbolAddress((void**)&inMh, g_inM_h);  cudaGetSymbolAddress((void**)&inMl, g_inM_l);
    cudaGetSymbolAddress((void**)&outMh,g_outM_h); cudaGetSymbolAddress((void**)&outMl,g_outM_l);
    cudaGetSymbolAddress((void**)&w3wh, g_w3w_h);  cudaGetSymbolAddress((void**)&w3wl, g_w3w_l);
    cudaGetSymbolAddress((void**)&w4wh, g_w4w_h);  cudaGetSymbolAddress((void**)&w4wl, g_w4w_l);
    cudaGetSymbolAddress((void**)&w5wh, g_w5w_h);  cudaGetSymbolAddress((void**)&w5wl, g_w5w_l);
    cudaGetSymbolAddress((void**)&w3uh, g_w3u_h);  cudaGetSymbolAddress((void**)&w3ul, g_w3u_l);
    cudaGetSymbolAddress((void**)&w5uh, g_w5u_h);  cudaGetSymbolAddress((void**)&w5ul, g_w5u_l);
    cudaGetSymbolAddress((void**)&ndTh, g_ndT_h);  cudaGetSymbolAddress((void**)&ndTl, g_ndT_l);
    cudaGetSymbolAddress((void**)&ndbh, g_ndb_h);  cudaGetSymbolAddress((void**)&ndbl, g_ndb_l);
    cudaGetSymbolAddress((void**)&ainh, g_ain_h);  cudaGetSymbolAddress((void**)&ainl, g_ain_l);
    cudaGetSymbolAddress((void**)&aouth,g_aout_h); cudaGetSymbolAddress((void**)&aoutl,g_aout_l);
    cudaGetSymbolAddress((void**)&rfh,  g_rf_h);   cudaGetSymbolAddress((void**)&rfl,  g_rf_l);

    cudaFuncSetAttribute(gemm_mma, cudaFuncAttributeMaxDynamicSharedMemorySize, GEMM_SMEM);

    const long ND = (long)NN*DD;     // 524288
    const int  BIG = 1 << 30;

    // init + one-time converts
    copy4<<<(BB*NN*DD/4 + 255)/256, 256>>>((const float4*)x, (float4*)nodes, BB*NN*DD/4);
    cvt_mat<<<(NN*NN/2 + 255)/256, 256>>>(in_m,  inMh,  inMl,  NN*NN);
    cvt_mat<<<(NN*NN/2 + 255)/256, 256>>>(out_m, outMh, outMl, NN*NN);
    cvt_mat<<<(DD*2*DD/2 + 255)/256, 256>>>(w3w, w3wh, w3wl, DD*2*DD);
    cvt_mat<<<(DD*2*DD/2 + 255)/256, 256>>>(w4w, w4wh, w4wl, DD*2*DD);
    cvt_mat<<<(DD*2*DD/2 + 255)/256, 256>>>(w5w, w5wh, w5wl, DD*2*DD);
    cvt_mat<<<(DD*DD/2 + 255)/256, 256>>>(w3u, w3uh, w3ul, DD*DD);
    cvt_mat<<<(DD*DD/2 + 255)/256, 256>>>(w5u, w5uh, w5ul, DD*DD);

    for (int step = 0; step < TIME_STEP; step++) {
        // nodes -> ndb hi/lo + ndT hi/lo
        transpose_cvt<<<dim3(DD/32, NN/32, BB), 256>>>(nodes);

        // a_in/a_out: M=1024, N=512, K=1024, batched over B; bf16 epilogue only
        dim3 gp(DD/128, NN/128, BB);
        gemm_mma<<<gp, 256, GEMM_SMEM>>>(inMh, inMl, inMh, inMl, BIG, NN,
                                         ndTh, ndTl, NN,
                                         nullptr, 0, ainh, ainl, DD,
                                         NN, 0L, ND, 0L, ND);
        gemm_mma<<<gp, 256, GEMM_SMEM>>>(outMh, outMl, outMh, outMl, BIG, NN,
                                         ndTh, ndTl, NN,
                                         nullptr, 0, aouth, aoutl, DD,
                                         NN, 0L, ND, 0L, ND);

        // gates j: [ain|aout] @ wjw^T, M=16384, N=512, K=1024 (split at 512)
        dim3 gg(DD/128, ROWS/128, 1);
        gemm_mma<<<gg, 256, GEMM_SMEM>>>(ainh, ainl, aouth, aoutl, DD, DD,
                                         w3wh, w3wl, 2*DD,
                                         gates + 0*DD, 3*DD, nullptr, nullptr, 0,
                                         2*DD, 0L, 0L, 0L, 0L);
        gemm_mma<<<gg, 256, GEMM_SMEM>>>(ainh, ainl, aouth, aoutl, DD, DD,
                                         w4wh, w4wl, 2*DD,
                                         gates + 1*DD, 3*DD, nullptr, nullptr, 0,
                                         2*DD, 0L, 0L, 0L, 0L);
        gemm_mma<<<gg, 256, GEMM_SMEM>>>(ainh, ainl, aouth, aoutl, DD, DD,
                                         w5wh, w5wl, 2*DD,
                                         gates + 2*DD, 3*DD, nullptr, nullptr, 0,
                                         2*DD, 0L, 0L, 0L, 0L);

        // u3 = nodes @ w3u^T, M=16384, N=512, K=512
        gemm_mma<<<gg, 256, GEMM_SMEM>>>(ndbh, ndbl, ndbh, ndbl, BIG, DD,
                                         w3uh, w3ul, DD,
                                         u3, DD, nullptr, nullptr, 0,
                                         DD, 0L, 0L, 0L, 0L);

        elem1<<<ROWS*DD/2/256, 256>>>(b3w, b3u, b4w);

        // t = (rv*f) @ w5u^T
        gemm_mma<<<gg, 256, GEMM_SMEM>>>(rfh, rfl, rfh, rfl, BIG, DD,
                                         w5uh, w5ul, DD,
                                         tt, DD, nullptr, nullptr, 0,
                                         DD, 0L, 0L, 0L, 0L);

        elem2<<<ROWS*DD/256, 256>>>(b5w, b5u);
    }

    copy4<<<(BB*NN*DD/4 + 255)/256, 256>>>((const float4*)nodes, (float4*)out, BB*NN*DD/4);
    copy4<<<(NN*NN/4 + 255)/256, 256>>>((const float4*)in_m,
                                        (float4*)(out + (long)BB*NN*DD), NN*NN/4);
}

// round 5
// speedup vs baseline: 1.8753x; 1.0854x over previous
#include <cuda_runtime.h>
#include <cuda_bf16.h>
#include <cstdint>
#include <math.h>

#define BB 16
#define NN 1024
#define DD 512
#define ROWS (BB*NN)          // 16384
#define TIME_STEP 3

// ---------------- fp32 scratch ----------------
__device__ float g_nodes[BB*NN*DD];
__device__ float g_u3   [BB*NN*DD];          // u3, then zv
__device__ float g_t    [BB*NN*DD];          // (rv*f)@w5u^T
__device__ float g_gates[BB*NN*3*DD];        // [16384][1536]

// ---------------- bf16 hi/lo operand buffers ----------------
__device__ __nv_bfloat16 g_inM_h [NN*NN], g_inM_l [NN*NN];
__device__ __nv_bfloat16 g_outM_h[NN*NN], g_outM_l[NN*NN];
__device__ __nv_bfloat16 g_wcat_h[3*DD*2*DD], g_wcat_l[3*DD*2*DD];  // [1536][1024]
__device__ __nv_bfloat16 g_w3u_h[DD*DD],   g_w3u_l[DD*DD];
__device__ __nv_bfloat16 g_w5u_h[DD*DD],   g_w5u_l[DD*DD];
__device__ __nv_bfloat16 g_ndT_h[BB*DD*NN], g_ndT_l[BB*DD*NN];   // [b][d][n]
__device__ __nv_bfloat16 g_ndb_h[BB*NN*DD], g_ndb_l[BB*NN*DD];   // [b][n][d]
__device__ __nv_bfloat16 g_ain_h[BB*NN*DD], g_ain_l[BB*NN*DD];
__device__ __nv_bfloat16 g_aout_h[BB*NN*DD], g_aout_l[BB*NN*DD];
__device__ __nv_bfloat16 g_rf_h [BB*NN*DD], g_rf_l [BB*NN*DD];

// ---------------- helpers ----------------
__device__ __forceinline__ uint32_t smem_u32(const void* p) {
    uint32_t a;
    asm("{ .reg .u64 t; cvta.to.shared.u64 t, %1; cvt.u32.u64 %0, t; }" : "=r"(a) : "l"(p));
    return a;
}
__device__ __forceinline__ void split2(float x, float y, uint32_t& hi, uint32_t& lo) {
    __nv_bfloat162 h = __floats2bfloat162_rn(x, y);   // low=x, high=y
    float rx = x - __bfloat162float(__low2bfloat16(h));
    float ry = y - __bfloat162float(__high2bfloat16(h));
    __nv_bfloat162 l = __floats2bfloat162_rn(rx, ry);
    hi = *(uint32_t*)&h; lo = *(uint32_t*)&l;
}
__device__ __forceinline__ void cpa16(uint32_t s, const void* g) {
    asm volatile("cp.async.cg.shared.global [%0], [%1], 16;" :: "r"(s), "l"(g));
}
__device__ __forceinline__ void cpa_commit() {
    asm volatile("cp.async.commit_group;" ::: "memory");
}
__device__ __forceinline__ void cpa_wait1() {
    asm volatile("cp.async.wait_group 1;" ::: "memory");
}
__device__ __forceinline__ void ldm_x4(uint32_t* r, uint32_t addr) {
    asm volatile("ldmatrix.sync.aligned.m8n8.x4.shared.b16 {%0,%1,%2,%3}, [%4];"
                 : "=r"(r[0]), "=r"(r[1]), "=r"(r[2]), "=r"(r[3]) : "r"(addr));
}
__device__ __forceinline__ void mma_bf16(float* d, const uint32_t* a, const uint32_t* b) {
    asm volatile("mma.sync.aligned.m16n8k16.row.col.f32.bf16.bf16.f32 "
                 "{%0,%1,%2,%3}, {%4,%5,%6,%7}, {%8,%9}, {%0,%1,%2,%3};"
                 : "+f"(d[0]), "+f"(d[1]), "+f"(d[2]), "+f"(d[3])
                 : "r"(a[0]), "r"(a[1]), "r"(a[2]), "r"(a[3]), "r"(b[0]), "r"(b[1]));
}

// ======================= bf16x3 mma.sync GEMM =======================
// C[m][n] = sum_k A'[m][k]*B[n][k]; A,B pre-split bf16 hi/lo, k-major.
// A' = A for k<ksplit else A2 at k-ksplit. blockIdx.z batch via aB/bB/cB/coB.
#define KC 32
#define RS 40                      // smem row stride in halves (80B, conflict-free)
#define TILE_HB (128*RS)           // halves per tile
#define STAGE_HB (4*TILE_HB)       // Ahi|Alo|Bhi|Blo
#define NSTAGE 3
#define GEMM_SMEM (NSTAGE*STAGE_HB*2)   // 122880 bytes

__device__ __forceinline__ void load_tile(uint32_t sbase, const __nv_bfloat16* g,
                                          int ld, int tid)
{
    int row = tid >> 2, cb = tid & 3;
    cpa16(sbase + (uint32_t)(row*RS + cb*8)*2, g + (long)row*ld + cb*8);
    cpa16(sbase + (uint32_t)((row+64)*RS + cb*8)*2, g + (long)(row+64)*ld + cb*8);
}

__global__ __launch_bounds__(256, 1)
void gemm_mma(const __nv_bfloat16* __restrict__ Ah, const __nv_bfloat16* __restrict__ Al,
              const __nv_bfloat16* __restrict__ A2h, const __nv_bfloat16* __restrict__ A2l,
              int ksplit, int lda,
              const __nv_bfloat16* __restrict__ Bh, const __nv_bfloat16* __restrict__ Bl,
              int ldb,
              float* __restrict__ C, int ldc,
              __nv_bfloat16* __restrict__ Coh, __nv_bfloat16* __restrict__ Col, int ldco,
              int Kd, long aB, long bB, long cB, long coB)
{
    extern __shared__ char smem[];
    const uint32_t sb = smem_u32(smem);

    const long z = blockIdx.z;
    Ah += z*aB; Al += z*aB; A2h += z*aB; A2l += z*aB;
    Bh += z*bB; Bl += z*bB;
    if (C)   C   += z*cB;
    if (Coh) { Coh += z*coB; Col += z*coB; }

    const int tid = threadIdx.x;
    const int wid = tid >> 5, lane = tid & 31;
    const int m0 = blockIdx.y * 128, n0 = blockIdx.x * 128;
    const int wrow = (wid & 1) * 64;
    const int wcol = (wid >> 1) * 32;

    float acc[4][4][4];
    #pragma unroll
    for (int i = 0; i < 4; i++)
        #pragma unroll
        for (int j = 0; j < 4; j++)
            #pragma unroll
            for (int k = 0; k < 4; k++) acc[i][j][k] = 0.f;

    const int KT = Kd / KC;

    auto load_stage = [&](int t) {
        int kbase = t * KC;
        const __nv_bfloat16 *pah = Ah, *pal = Al;
        int ka = kbase;
        if (kbase >= ksplit) { pah = A2h; pal = A2l; ka -= ksplit; }
        uint32_t s = sb + (uint32_t)(t % NSTAGE) * STAGE_HB * 2;
        load_tile(s,               pah + (long)m0*lda + ka,    lda, tid);
        load_tile(s + TILE_HB*2,   pal + (long)m0*lda + ka,    lda, tid);
        load_tile(s + 2*TILE_HB*2, Bh  + (long)n0*ldb + kbase, ldb, tid);
        load_tile(s + 3*TILE_HB*2, Bl  + (long)n0*ldb + kbase, ldb, tid);
    };

    load_stage(0); cpa_commit();
    load_stage(1); cpa_commit();

    const int ar = lane & 15, acg = lane >> 4;
    const int bg = lane >> 3, bl8 = lane & 7;

    for (int t = 0; t < KT; t++) {
        cpa_wait1();          // stage t complete (thread-local)
        __syncthreads();      // publish stage t; all warps done with stage t-1
        if (t + 2 < KT) load_stage(t + 2);   // overwrites buffer (t-1)%3: safe
        cpa_commit();         // always: keeps group accounting uniform

        const uint32_t s = sb + (uint32_t)(t % NSTAGE) * STAGE_HB * 2;
        const uint32_t sAh = s, sAl = s + TILE_HB*2;
        const uint32_t sBh = s + 2*TILE_HB*2, sBl = s + 3*TILE_HB*2;

        #pragma unroll
        for (int ks = 0; ks < 2; ks++) {
            uint32_t ah[4][4], al[4][4], bh[2][4], bl[2][4];
            #pragma unroll
            for (int mb = 0; mb < 4; mb++) {
                uint32_t off = (uint32_t)((wrow + mb*16 + ar)*RS + ks*16 + acg*8)*2;
                ldm_x4(ah[mb], sAh + off);
                ldm_x4(al[mb], sAl + off);
            }
            #pragma unroll
            for (int nb2 = 0; nb2 < 2; nb2++) {
                int rowb = wcol + nb2*16 + ((bg >> 1) & 1)*8 + bl8;
                int kcb  = ks*16 + (bg & 1)*8;
                uint32_t off = (uint32_t)(rowb*RS + kcb)*2;
                ldm_x4(bh[nb2], sBh + off);
                ldm_x4(bl[nb2], sBl + off);
            }
            #pragma unroll
            for (int mb = 0; mb < 4; mb++)
                #pragma unroll
                for (int nb = 0; nb < 4; nb++) {
                    const uint32_t* ph = &bh[nb >> 1][(nb & 1)*2];
                    const uint32_t* pl = &bl[nb >> 1][(nb & 1)*2];
                    mma_bf16(acc[mb][nb], ah[mb], ph);
                    mma_bf16(acc[mb][nb], ah[mb], pl);
                    mma_bf16(acc[mb][nb], al[mb], ph);
                }
        }
    }

    // ---- epilogue ----
    const int r0 = lane >> 2, c0 = (lane & 3)*2;
    #pragma unroll
    for (int mb = 0; mb < 4; mb++) {
        #pragma unroll
        for (int nb = 0; nb < 4; nb++) {
            long row = m0 + wrow + mb*16 + r0;
            int  col = n0 + wcol + nb*8 + c0;
            float* a = acc[mb][nb];
            if (C) {
                *(float2*)&C[row*ldc + col]     = make_float2(a[0], a[1]);
                *(float2*)&C[(row+8)*ldc + col] = make_float2(a[2], a[3]);
            }
            if (Coh) {
                uint32_t hi, lo;
                split2(a[0], a[1], hi, lo);
                *(uint32_t*)&Coh[row*ldco + col] = hi;
                *(uint32_t*)&Col[row*ldco + col] = lo;
                split2(a[2], a[3], hi, lo);
                *(uint32_t*)&Coh[(row+8)*ldco + col] = hi;
                *(uint32_t*)&Col[(row+8)*ldco + col] = lo;
            }
        }
    }
}

// ---------------- fused one-time converter ----------------
__global__ void cvt_all(const float* __restrict__ in_m, const float* __restrict__ out_m,
                        const float* __restrict__ w3w, const float* __restrict__ w4w,
                        const float* __restrict__ w5w, const float* __restrict__ w3u,
                        const float* __restrict__ w5u)
{
    long p = ((long)blockIdx.x*blockDim.x + threadIdx.x) * 2;
    const long S0 = 1048576, S1 = 2097152, S2 = S1 + 524288, S3 = S2 + 524288,
               S4 = S3 + 524288, S5 = S4 + 262144, S6 = S5 + 262144;
    if (p >= S6) return;
    const float* src; __nv_bfloat16 *dh, *dl; long off;
    if      (p < S0) { src = in_m;  dh = g_inM_h;  dl = g_inM_l;  off = p; }
    else if (p < S1) { src = out_m; dh = g_outM_h; dl = g_outM_l; off = p - S0; }
    else if (p < S2) { src = w3w; dh = g_wcat_h;           dl = g_wcat_l;           off = p - S1; }
    else if (p < S3) { src = w4w; dh = g_wcat_h + 524288;  dl = g_wcat_l + 524288;  off = p - S2; }
    else if (p < S4) { src = w5w; dh = g_wcat_h + 1048576; dl = g_wcat_l + 1048576; off = p - S3; }
    else if (p < S5) { src = w3u; dh = g_w3u_h; dl = g_w3u_l; off = p - S4; }
    else             { src = w5u; dh = g_w5u_h; dl = g_w5u_l; off = p - S5; }
    float2 v = *(const float2*)&src[off];
    uint32_t h, l;
    split2(v.x, v.y, h, l);
    *(uint32_t*)&dh[off] = h;
    *(uint32_t*)&dl[off] = l;
}

// nodes [b][n][d] fp32 -> ndb hi/lo (straight) + ndT hi/lo (transposed [b][d][n])
__global__ void transpose_cvt(const float* __restrict__ src)
{
    __shared__ float tile[32][33];
    const int b = blockIdx.z;
    const int d0 = blockIdx.x*32, n0 = blockIdx.y*32;
    const float* s = src + (long)b*NN*DD;
    const int tid = threadIdx.x;
    #pragma unroll
    for (int i = 0; i < 4; i++) {
        int p = tid + i*256, n = p >> 5, d = p & 31;
        tile[n][d] = s[(long)(n0+n)*DD + d0 + d];
    }
    __syncthreads();
    #pragma unroll
    for (int i = 0; i < 2; i++) {
        int p = tid + i*256, n = p >> 4, dp = p & 15;
        uint32_t h, l;
        split2(tile[n][dp*2], tile[n][dp*2+1], h, l);
        long o = ((long)b*NN + n0 + n)*DD + d0 + dp*2;
        *(uint32_t*)&g_ndb_h[o] = h; *(uint32_t*)&g_ndb_l[o] = l;
    }
    #pragma unroll
    for (int i = 0; i < 2; i++) {
        int p = tid + i*256, d = p >> 4, np = p & 15;
        uint32_t h, l;
        split2(tile[np*2][d], tile[np*2+1][d], h, l);
        long o = ((long)b*DD + d0 + d)*NN + n0 + np*2;
        *(uint32_t*)&g_ndT_h[o] = h; *(uint32_t*)&g_ndT_l[o] = l;
    }
}

// ---------------- elementwise ----------------
__global__ void elem1(const float* __restrict__ b3w, const float* __restrict__ b3u,
                      const float* __restrict__ b4w)
{
    int p = blockIdx.x*blockDim.x + threadIdx.x;
    long i = (long)p*2;
    int row = (int)(i >> 9), e = (int)(i & 511);
    float2 u = *(const float2*)&g_u3[i];
    float2 f = *(const float2*)&g_nodes[i];
    float g3a = g_gates[(long)row*1536 + e],       g3b = g_gates[(long)row*1536 + e + 1];
    float g4a = g_gates[(long)row*1536 + 512 + e], g4b = g_gates[(long)row*1536 + 512 + e + 1];
    float ua = u.x + b3u[e], ub = u.y + b3u[e+1];
    float za = 1.f/(1.f + expf(-(g3a + b3w[e] + ua)));
    float zb = 1.f/(1.f + expf(-(g3b + b3w[e+1] + ub)));
    float ra = 1.f/(1.f + expf(-(g4a + b4w[e] + ua)));
    float rb = 1.f/(1.f + expf(-(g4b + b4w[e+1] + ub)));
    *(float2*)&g_u3[i] = make_float2(za, zb);
    uint32_t h, l;
    split2(ra*f.x, rb*f.y, h, l);
    *(uint32_t*)&g_rf_h[i] = h;
    *(uint32_t*)&g_rf_l[i] = l;
}

__global__ void elem2(const float* __restrict__ b5w, const float* __restrict__ b5u)
{
    long i = (long)blockIdx.x*blockDim.x + threadIdx.x;
    int row = (int)(i >> 9), e = (int)(i & 511);
    float t  = g_t[i];
    float g5 = g_gates[(long)row*1536 + 1024 + e];
    float hv = tanhf(g5 + b5w[e] + t + b5u[e]);
    float z  = g_u3[i];
    float f  = g_nodes[i];
    g_nodes[i] = (1.f - z)*f + z*hv;
}

__global__ void copy4(const float4* __restrict__ src, float4* __restrict__ dst, int n4)
{
    int i = blockIdx.x*blockDim.x + threadIdx.x;
    if (i < n4) dst[i] = src[i];
}

// ---------------- host launcher ----------------
extern "C" void kernel_launch(void* const* d_in, const int* in_sizes, int n_in,
                              void* d_out, int out_size)
{
    (void)in_sizes; (void)n_in; (void)out_size;
    const float* x     = (const float*)d_in[0];
    const float* in_m  = (const float*)d_in[1];
    const float* out_m = (const float*)d_in[2];
    const float* w3w   = (const float*)d_in[3];
    const float* b3w   = (const float*)d_in[4];
    const float* w3u   = (const float*)d_in[5];
    const float* b3u   = (const float*)d_in[6];
    const float* w4w   = (const float*)d_in[7];
    const float* b4w   = (const float*)d_in[8];
    const float* w5w   = (const float*)d_in[9];
    const float* b5w   = (const float*)d_in[10];
    const float* w5u   = (const float*)d_in[11];
    const float* b5u   = (const float*)d_in[12];
    float* out = (float*)d_out;

    float *nodes, *u3, *tt, *gates;
    cudaGetSymbolAddress((void**)&nodes, g_nodes);
    cudaGetSymbolAddress((void**)&u3,    g_u3);
    cudaGetSymbolAddress((void**)&tt,    g_t);
    cudaGetSymbolAddress((void**)&gates, g_gates);

    __nv_bfloat16 *inMh,*inMl,*outMh,*outMl,*wcath,*wcatl;
    __nv_bfloat16 *w3uh,*w3ul,*w5uh,*w5ul,*ndTh,*ndTl,*ndbh,*ndbl;
    __nv_bfloat16 *ainh,*ainl,*aouth,*aoutl,*rfh,*rfl;
    cudaGetSymbolAddress((void**)&inMh, g_inM_h);  cudaGetSymbolAddress((void**)&inMl, g_inM_l);
    cudaGetSymbolAddress((void**)&outMh,g_outM_h); cudaGetSymbolAddress((void**)&outMl,g_outM_l);
    cudaGetSymbolAddress((void**)&wcath,g_wcat_h); cudaGetSymbolAddress((void**)&wcatl,g_wcat_l);
    cudaGetSymbolAddress((void**)&w3uh, g_w3u_h);  cudaGetSymbolAddress((void**)&w3ul, g_w3u_l);
    cudaGetSymbolAddress((void**)&w5uh, g_w5u_h);  cudaGetSymbolAddress((void**)&w5ul, g_w5u_l);
    cudaGetSymbolAddress((void**)&ndTh, g_ndT_h);  cudaGetSymbolAddress((void**)&ndTl, g_ndT_l);
    cudaGetSymbolAddress((void**)&ndbh, g_ndb_h);  cudaGetSymbolAddress((void**)&ndbl, g_ndb_l);
    cudaGetSymbolAddress((void**)&ainh, g_ain_h);  cudaGetSymbolAddress((void**)&ainl, g_ain_l);
    cudaGetSymbolAddress((void**)&aouth,g_aout_h); cudaGetSymbolAddress((void**)&aoutl,g_aout_l);
    cudaGetSymbolAddress((void**)&rfh,  g_rf_h);   cudaGetSymbolAddress((void**)&rfl,  g_rf_l);

    cudaFuncSetAttribute(gemm_mma, cudaFuncAttributeMaxDynamicSharedMemorySize, GEMM_SMEM);

    const long ND = (long)NN*DD;     // 524288
    const int  BIG = 1 << 30;

    copy4<<<(BB*NN*DD/4 + 255)/256, 256>>>((const float4*)x, (float4*)nodes, BB*NN*DD/4);
    cvt_all<<<8192, 256>>>(in_m, out_m, w3w, w4w, w5w, w3u, w5u);

    for (int step = 0; step < TIME_STEP; step++) {
        transpose_cvt<<<dim3(DD/32, NN/32, BB), 256>>>(nodes);

        // a_in/a_out: M=1024, N=512, K=1024, batched over B; bf16 epilogue only
        dim3 gp(DD/128, NN/128, BB);
        gemm_mma<<<gp, 256, GEMM_SMEM>>>(inMh, inMl, inMh, inMl, BIG, NN,
                                         ndTh, ndTl, NN,
                                         nullptr, 0, ainh, ainl, DD,
                                         NN, 0L, ND, 0L, ND);
        gemm_mma<<<gp, 256, GEMM_SMEM>>>(outMh, outMl, outMh, outMl, BIG, NN,
                                         ndTh, ndTl, NN,
                                         nullptr, 0, aouth, aoutl, DD,
                                         NN, 0L, ND, 0L, ND);

        // fused gates: [ain|aout] @ wcat^T, M=16384, N=1536, K=1024 (split at 512)
        dim3 gg3(3*DD/128, ROWS/128, 1);   // (12, 128)
        gemm_mma<<<gg3, 256, GEMM_SMEM>>>(ainh, ainl, aouth, aoutl, DD, DD,
                                          wcath, wcatl, 2*DD,
                                          gates, 3*DD, nullptr, nullptr, 0,
                                          2*DD, 0L, 0L, 0L, 0L);

        // u3 = nodes @ w3u^T, M=16384, N=512, K=512
        dim3 gg(DD/128, ROWS/128, 1);
        gemm_mma<<<gg, 256, GEMM_SMEM>>>(ndbh, ndbl, ndbh, ndbl, BIG, DD,
                                         w3uh, w3ul, DD,
                                         u3, DD, nullptr, nullptr, 0,
                                         DD, 0L, 0L, 0L, 0L);

        elem1<<<ROWS*DD/2/256, 256>>>(b3w, b3u, b4w);

        // t = (rv*f) @ w5u^T
        gemm_mma<<<gg, 256, GEMM_SMEM>>>(rfh, rfl, rfh, rfl, BIG, DD,
                                         w5uh, w5ul, DD,
                                         tt, DD, nullptr, nullptr, 0,
                                         DD, 0L, 0L, 0L, 0L);

        elem2<<<ROWS*DD/256, 256>>>(b5w, b5u);
    }

    copy4<<<(BB*NN*DD/4 + 255)/256, 256>>>((const float4*)nodes, (float4*)out, BB*NN*DD/4);
    copy4<<<(NN*NN/4 + 255)/256, 256>>>((const float4*)in_m,
                                        (float4*)(out + (long)BB*NN*DD), NN*NN/4);
}

// round 6
// speedup vs baseline: 1.9555x; 1.0428x over previous
#include <cuda_runtime.h>
#include <cuda_bf16.h>
#include <cstdint>
#include <math.h>

#define BB 16
#define NN 1024
#define DD 512
#define ROWS (BB*NN)          // 16384
#define TIME_STEP 3

// ---------------- fp32 scratch ----------------
__device__ float g_nodes[BB*NN*DD];
__device__ float g_u3   [BB*NN*DD];          // u3, then zv
__device__ float g_t    [BB*NN*DD];          // (rv*f)@w5u^T
__device__ float g_gates[BB*NN*3*DD];        // [16384][1536]

// ---------------- bf16 hi/lo operand buffers ----------------
__device__ __nv_bfloat16 g_inM_h [NN*NN], g_inM_l [NN*NN];
__device__ __nv_bfloat16 g_outM_h[NN*NN], g_outM_l[NN*NN];
__device__ __nv_bfloat16 g_wcat_h[3*DD*2*DD], g_wcat_l[3*DD*2*DD];  // [1536][1024]
__device__ __nv_bfloat16 g_w3u_h[DD*DD],   g_w3u_l[DD*DD];
__device__ __nv_bfloat16 g_w5u_h[DD*DD],   g_w5u_l[DD*DD];
__device__ __nv_bfloat16 g_ndT_h[BB*DD*NN], g_ndT_l[BB*DD*NN];   // [b][d][n]
__device__ __nv_bfloat16 g_ndb_h[BB*NN*DD], g_ndb_l[BB*NN*DD];   // [b][n][d]
__device__ __nv_bfloat16 g_ain_h[BB*NN*DD], g_ain_l[BB*NN*DD];
__device__ __nv_bfloat16 g_aout_h[BB*NN*DD], g_aout_l[BB*NN*DD];
__device__ __nv_bfloat16 g_rf_h [BB*NN*DD], g_rf_l [BB*NN*DD];

// ---------------- helpers ----------------
__device__ __forceinline__ uint32_t smem_u32(const void* p) {
    uint32_t a;
    asm("{ .reg .u64 t; cvta.to.shared.u64 t, %1; cvt.u32.u64 %0, t; }" : "=r"(a) : "l"(p));
    return a;
}
__device__ __forceinline__ void split2(float x, float y, uint32_t& hi, uint32_t& lo) {
    __nv_bfloat162 h = __floats2bfloat162_rn(x, y);   // low=x, high=y
    float rx = x - __bfloat162float(__low2bfloat16(h));
    float ry = y - __bfloat162float(__high2bfloat16(h));
    __nv_bfloat162 l = __floats2bfloat162_rn(rx, ry);
    hi = *(uint32_t*)&h; lo = *(uint32_t*)&l;
}
__device__ __forceinline__ void cpa16(uint32_t s, const void* g) {
    asm volatile("cp.async.cg.shared.global [%0], [%1], 16;" :: "r"(s), "l"(g));
}
__device__ __forceinline__ void cpa_commit() {
    asm volatile("cp.async.commit_group;" ::: "memory");
}
__device__ __forceinline__ void cpa_wait2() {
    asm volatile("cp.async.wait_group 2;" ::: "memory");
}
__device__ __forceinline__ void ldm_x4(uint32_t* r, uint32_t addr) {
    asm volatile("ldmatrix.sync.aligned.m8n8.x4.shared.b16 {%0,%1,%2,%3}, [%4];"
                 : "=r"(r[0]), "=r"(r[1]), "=r"(r[2]), "=r"(r[3]) : "r"(addr));
}
__device__ __forceinline__ void mma_bf16(float* d, const uint32_t* a, const uint32_t* b) {
    asm volatile("mma.sync.aligned.m16n8k16.row.col.f32.bf16.bf16.f32 "
                 "{%0,%1,%2,%3}, {%4,%5,%6,%7}, {%8,%9}, {%0,%1,%2,%3};"
                 : "+f"(d[0]), "+f"(d[1]), "+f"(d[2]), "+f"(d[3])
                 : "r"(a[0]), "r"(a[1]), "r"(a[2]), "r"(a[3]), "r"(b[0]), "r"(b[1]));
}

// ======================= bf16x3 mma.sync GEMM =======================
// C[m][n] = sum_k A'[m][k]*B[n][k]; A,B pre-split bf16 hi/lo, k-major.
// msel=0: A' = A for k<ksplit else A2 at k-ksplit; batch z via aB/bB/cB/coB.
// msel=1: matrix pair (A vs A2) chosen by z>=16; batch = z&15; epilogue goes
//         to (Coh,Col) for z<16 and (Co2h,Co2l) for z>=16. ksplit unused.
#define KC 32
#define RS 40                      // smem row stride in halves (80B, conflict-free)
#define TILE_HB (128*RS)           // halves per tile
#define STAGE_HB (4*TILE_HB)       // Ahi|Alo|Bhi|Blo
#define NSTAGE 4
#define GEMM_SMEM (NSTAGE*STAGE_HB*2)   // 163840 bytes

__device__ __forceinline__ void load_tile(uint32_t sbase, const __nv_bfloat16* g,
                                          int ld, int tid)
{
    int row = tid >> 2, cb = tid & 3;
    cpa16(sbase + (uint32_t)(row*RS + cb*8)*2, g + (long)row*ld + cb*8);
    cpa16(sbase + (uint32_t)((row+64)*RS + cb*8)*2, g + (long)(row+64)*ld + cb*8);
}

__global__ __launch_bounds__(256, 1)
void gemm_mma(const __nv_bfloat16* __restrict__ Ah, const __nv_bfloat16* __restrict__ Al,
              const __nv_bfloat16* __restrict__ A2h, const __nv_bfloat16* __restrict__ A2l,
              int ksplit, int lda, int msel,
              const __nv_bfloat16* __restrict__ Bh, const __nv_bfloat16* __restrict__ Bl,
              int ldb,
              float* __restrict__ C, int ldc,
              __nv_bfloat16* __restrict__ Coh, __nv_bfloat16* __restrict__ Col,
              __nv_bfloat16* __restrict__ Co2h, __nv_bfloat16* __restrict__ Co2l,
              int ldco,
              int Kd, long aB, long bB, long cB, long coB)
{
    extern __shared__ char smem[];
    const uint32_t sb = smem_u32(smem);

    long z = blockIdx.z;
    if (msel) {
        if (z >= 16) { Ah = A2h; Al = A2l; Coh = Co2h; Col = Co2l; z -= 16; }
        A2h = Ah; A2l = Al;
        ksplit = 1 << 30;
    }
    Ah += z*aB; Al += z*aB; A2h += z*aB; A2l += z*aB;
    Bh += z*bB; Bl += z*bB;
    if (C)   C   += z*cB;
    if (Coh) { Coh += z*coB; Col += z*coB; }

    const int tid = threadIdx.x;
    const int wid = tid >> 5, lane = tid & 31;
    const int m0 = blockIdx.y * 128, n0 = blockIdx.x * 128;
    const int wrow = (wid & 1) * 64;
    const int wcol = (wid >> 1) * 32;

    float acc[4][4][4];
    #pragma unroll
    for (int i = 0; i < 4; i++)
        #pragma unroll
        for (int j = 0; j < 4; j++)
            #pragma unroll
            for (int k = 0; k < 4; k++) acc[i][j][k] = 0.f;

    const int KT = Kd / KC;

    auto load_stage = [&](int t) {
        int kbase = t * KC;
        const __nv_bfloat16 *pah = Ah, *pal = Al;
        int ka = kbase;
        if (kbase >= ksplit) { pah = A2h; pal = A2l; ka -= ksplit; }
        uint32_t s = sb + (uint32_t)(t % NSTAGE) * STAGE_HB * 2;
        load_tile(s,               pah + (long)m0*lda + ka,    lda, tid);
        load_tile(s + TILE_HB*2,   pal + (long)m0*lda + ka,    lda, tid);
        load_tile(s + 2*TILE_HB*2, Bh  + (long)n0*ldb + kbase, ldb, tid);
        load_tile(s + 3*TILE_HB*2, Bl  + (long)n0*ldb + kbase, ldb, tid);
    };

    load_stage(0); cpa_commit();
    load_stage(1); cpa_commit();
    load_stage(2); cpa_commit();

    const int ar = lane & 15, acg = lane >> 4;
    const int bg = lane >> 3, bl8 = lane & 7;

    for (int t = 0; t < KT; t++) {
        cpa_wait2();          // stage t complete (<=2 newer groups pending)
        __syncthreads();      // publish stage t; all warps done with stage t-1
        if (t + 3 < KT) load_stage(t + 3);   // overwrites buffer (t-1)%4: safe
        cpa_commit();         // keep group accounting uniform

        const uint32_t s = sb + (uint32_t)(t % NSTAGE) * STAGE_HB * 2;
        const uint32_t sAh = s, sAl = s + TILE_HB*2;
        const uint32_t sBh = s + 2*TILE_HB*2, sBl = s + 3*TILE_HB*2;

        #pragma unroll
        for (int ks = 0; ks < 2; ks++) {
            uint32_t ah[4][4], al[4][4], bh[2][4], bl[2][4];
            #pragma unroll
            for (int mb = 0; mb < 4; mb++) {
                uint32_t off = (uint32_t)((wrow + mb*16 + ar)*RS + ks*16 + acg*8)*2;
                ldm_x4(ah[mb], sAh + off);
                ldm_x4(al[mb], sAl + off);
            }
            #pragma unroll
            for (int nb2 = 0; nb2 < 2; nb2++) {
                int rowb = wcol + nb2*16 + ((bg >> 1) & 1)*8 + bl8;
                int kcb  = ks*16 + (bg & 1)*8;
                uint32_t off = (uint32_t)(rowb*RS + kcb)*2;
                ldm_x4(bh[nb2], sBh + off);
                ldm_x4(bl[nb2], sBl + off);
            }
            #pragma unroll
            for (int mb = 0; mb < 4; mb++)
                #pragma unroll
                for (int nb = 0; nb < 4; nb++) {
                    const uint32_t* ph = &bh[nb >> 1][(nb & 1)*2];
                    const uint32_t* pl = &bl[nb >> 1][(nb & 1)*2];
                    mma_bf16(acc[mb][nb], ah[mb], ph);
                    mma_bf16(acc[mb][nb], ah[mb], pl);
                    mma_bf16(acc[mb][nb], al[mb], ph);
                }
        }
    }

    // ---- epilogue ----
    const int r0 = lane >> 2, c0 = (lane & 3)*2;
    #pragma unroll
    for (int mb = 0; mb < 4; mb++) {
        #pragma unroll
        for (int nb = 0; nb < 4; nb++) {
            long row = m0 + wrow + mb*16 + r0;
            int  col = n0 + wcol + nb*8 + c0;
            float* a = acc[mb][nb];
            if (C) {
                *(float2*)&C[row*ldc + col]     = make_float2(a[0], a[1]);
                *(float2*)&C[(row+8)*ldc + col] = make_float2(a[2], a[3]);
            }
            if (Coh) {
                uint32_t hi, lo;
                split2(a[0], a[1], hi, lo);
                *(uint32_t*)&Coh[row*ldco + col] = hi;
                *(uint32_t*)&Col[row*ldco + col] = lo;
                split2(a[2], a[3], hi, lo);
                *(uint32_t*)&Coh[(row+8)*ldco + col] = hi;
                *(uint32_t*)&Col[(row+8)*ldco + col] = lo;
            }
        }
    }
}

// ---------------- fused one-time converter ----------------
__global__ void cvt_all(const float* __restrict__ in_m, const float* __restrict__ out_m,
                        const float* __restrict__ w3w, const float* __restrict__ w4w,
                        const float* __restrict__ w5w, const float* __restrict__ w3u,
                        const float* __restrict__ w5u)
{
    long p = ((long)blockIdx.x*blockDim.x + threadIdx.x) * 2;
    const long S0 = 1048576, S1 = 2097152, S2 = S1 + 524288, S3 = S2 + 524288,
               S4 = S3 + 524288, S5 = S4 + 262144, S6 = S5 + 262144;
    if (p >= S6) return;
    const float* src; __nv_bfloat16 *dh, *dl; long off;
    if      (p < S0) { src = in_m;  dh = g_inM_h;  dl = g_inM_l;  off = p; }
    else if (p < S1) { src = out_m; dh = g_outM_h; dl = g_outM_l; off = p - S0; }
    else if (p < S2) { src = w3w; dh = g_wcat_h;           dl = g_wcat_l;           off = p - S1; }
    else if (p < S3) { src = w4w; dh = g_wcat_h + 524288;  dl = g_wcat_l + 524288;  off = p - S2; }
    else if (p < S4) { src = w5w; dh = g_wcat_h + 1048576; dl = g_wcat_l + 1048576; off = p - S3; }
    else if (p < S5) { src = w3u; dh = g_w3u_h; dl = g_w3u_l; off = p - S4; }
    else             { src = w5u; dh = g_w5u_h; dl = g_w5u_l; off = p - S5; }
    float2 v = *(const float2*)&src[off];
    uint32_t h, l;
    split2(v.x, v.y, h, l);
    *(uint32_t*)&dh[off] = h;
    *(uint32_t*)&dl[off] = l;
}

// nodes [b][n][d] fp32 -> ndb hi/lo (straight) + ndT hi/lo (transposed [b][d][n])
__global__ void transpose_cvt(const float* __restrict__ src)
{
    __shared__ float tile[32][33];
    const int b = blockIdx.z;
    const int d0 = blockIdx.x*32, n0 = blockIdx.y*32;
    const float* s = src + (long)b*NN*DD;
    const int tid = threadIdx.x;
    #pragma unroll
    for (int i = 0; i < 4; i++) {
        int p = tid + i*256, n = p >> 5, d = p & 31;
        tile[n][d] = s[(long)(n0+n)*DD + d0 + d];
    }
    __syncthreads();
    #pragma unroll
    for (int i = 0; i < 2; i++) {
        int p = tid + i*256, n = p >> 4, dp = p & 15;
        uint32_t h, l;
        split2(tile[n][dp*2], tile[n][dp*2+1], h, l);
        long o = ((long)b*NN + n0 + n)*DD + d0 + dp*2;
        *(uint32_t*)&g_ndb_h[o] = h; *(uint32_t*)&g_ndb_l[o] = l;
    }
    #pragma unroll
    for (int i = 0; i < 2; i++) {
        int p = tid + i*256, d = p >> 4, np = p & 15;
        uint32_t h, l;
        split2(tile[np*2][d], tile[np*2+1][d], h, l);
        long o = ((long)b*DD + d0 + d)*NN + n0 + np*2;
        *(uint32_t*)&g_ndT_h[o] = h; *(uint32_t*)&g_ndT_l[o] = l;
    }
}

// ---------------- elementwise ----------------
__global__ void elem1(const float* __restrict__ b3w, const float* __restrict__ b3u,
                      const float* __restrict__ b4w)
{
    int p = blockIdx.x*blockDim.x + threadIdx.x;
    long i = (long)p*2;
    int row = (int)(i >> 9), e = (int)(i & 511);
    float2 u = *(const float2*)&g_u3[i];
    float2 f = *(const float2*)&g_nodes[i];
    float g3a = g_gates[(long)row*1536 + e],       g3b = g_gates[(long)row*1536 + e + 1];
    float g4a = g_gates[(long)row*1536 + 512 + e], g4b = g_gates[(long)row*1536 + 512 + e + 1];
    float ua = u.x + b3u[e], ub = u.y + b3u[e+1];
    float za = 1.f/(1.f + expf(-(g3a + b3w[e] + ua)));
    float zb = 1.f/(1.f + expf(-(g3b + b3w[e+1] + ub)));
    float ra = 1.f/(1.f + expf(-(g4a + b4w[e] + ua)));
    float rb = 1.f/(1.f + expf(-(g4b + b4w[e+1] + ub)));
    *(float2*)&g_u3[i] = make_float2(za, zb);
    uint32_t h, l;
    split2(ra*f.x, rb*f.y, h, l);
    *(uint32_t*)&g_rf_h[i] = h;
    *(uint32_t*)&g_rf_l[i] = l;
}

__global__ void elem2(const float* __restrict__ b5w, const float* __restrict__ b5u)
{
    long i = (long)blockIdx.x*blockDim.x + threadIdx.x;
    int row = (int)(i >> 9), e = (int)(i & 511);
    float t  = g_t[i];
    float g5 = g_gates[(long)row*1536 + 1024 + e];
    float hv = tanhf(g5 + b5w[e] + t + b5u[e]);
    float z  = g_u3[i];
    float f  = g_nodes[i];
    g_nodes[i] = (1.f - z)*f + z*hv;
}

__global__ void copy4(const float4* __restrict__ src, float4* __restrict__ dst, int n4)
{
    int i = blockIdx.x*blockDim.x + threadIdx.x;
    if (i < n4) dst[i] = src[i];
}

// ---------------- host launcher ----------------
extern "C" void kernel_launch(void* const* d_in, const int* in_sizes, int n_in,
                              void* d_out, int out_size)
{
    (void)in_sizes; (void)n_in; (void)out_size;
    const float* x     = (const float*)d_in[0];
    const float* in_m  = (const float*)d_in[1];
    const float* out_m = (const float*)d_in[2];
    const float* w3w   = (const float*)d_in[3];
    const float* b3w   = (const float*)d_in[4];
    const float* w3u   = (const float*)d_in[5];
    const float* b3u   = (const float*)d_in[6];
    const float* w4w   = (const float*)d_in[7];
    const float* b4w   = (const float*)d_in[8];
    const float* w5w   = (const float*)d_in[9];
    const float* b5w   = (const float*)d_in[10];
    const float* w5u   = (const float*)d_in[11];
    const float* b5u   = (const float*)d_in[12];
    float* out = (float*)d_out;

    float *nodes, *u3, *tt, *gates;
    cudaGetSymbolAddress((void**)&nodes, g_nodes);
    cudaGetSymbolAddress((void**)&u3,    g_u3);
    cudaGetSymbolAddress((void**)&tt,    g_t);
    cudaGetSymbolAddress((void**)&gates, g_gates);

    __nv_bfloat16 *inMh,*inMl,*outMh,*outMl,*wcath,*wcatl;
    __nv_bfloat16 *w3uh,*w3ul,*w5uh,*w5ul,*ndTh,*ndTl,*ndbh,*ndbl;
    __nv_bfloat16 *ainh,*ainl,*aouth,*aoutl,*rfh,*rfl;
    cudaGetSymbolAddress((void**)&inMh, g_inM_h);  cudaGetSymbolAddress((void**)&inMl, g_inM_l);
    cudaGetSymbolAddress((void**)&outMh,g_outM_h); cudaGetSymbolAddress((void**)&outMl,g_outM_l);
    cudaGetSymbolAddress((void**)&wcath,g_wcat_h); cudaGetSymbolAddress((void**)&wcatl,g_wcat_l);
    cudaGetSymbolAddress((void**)&w3uh, g_w3u_h);  cudaGetSymbolAddress((void**)&w3ul, g_w3u_l);
    cudaGetSymbolAddress((void**)&w5uh, g_w5u_h);  cudaGetSymbolAddress((void**)&w5ul, g_w5u_l);
    cudaGetSymbolAddress((void**)&ndTh, g_ndT_h);  cudaGetSymbolAddress((void**)&ndTl, g_ndT_l);
    cudaGetSymbolAddress((void**)&ndbh, g_ndb_h);  cudaGetSymbolAddress((void**)&ndbl, g_ndb_l);
    cudaGetSymbolAddress((void**)&ainh, g_ain_h);  cudaGetSymbolAddress((void**)&ainl, g_ain_l);
    cudaGetSymbolAddress((void**)&aouth,g_aout_h); cudaGetSymbolAddress((void**)&aoutl,g_aout_l);
    cudaGetSymbolAddress((void**)&rfh,  g_rf_h);   cudaGetSymbolAddress((void**)&rfl,  g_rf_l);

    cudaFuncSetAttribute(gemm_mma, cudaFuncAttributeMaxDynamicSharedMemorySize, GEMM_SMEM);

    const long ND = (long)NN*DD;     // 524288
    const int  BIG = 1 << 30;

    copy4<<<(BB*NN*DD/4 + 255)/256, 256>>>((const float4*)x, (float4*)nodes, BB*NN*DD/4);
    cvt_all<<<8192, 256>>>(in_m, out_m, w3w, w4w, w5w, w3u, w5u);

    for (int step = 0; step < TIME_STEP; step++) {
        transpose_cvt<<<dim3(DD/32, NN/32, BB), 256>>>(nodes);

        // fused a_in + a_out: M=1024, N=512, K=1024, z=0..31 (z>=16 -> out_matrix)
        dim3 gp(DD/128, NN/128, 2*BB);
        gemm_mma<<<gp, 256, GEMM_SMEM>>>(inMh, inMl, outMh, outMl, BIG, NN, 1,
                                         ndTh, ndTl, NN,
                                         nullptr, 0,
                                         ainh, ainl, aouth, aoutl, DD,
                                         NN, 0L, ND, 0L, ND);

        // fused gates: [ain|aout] @ wcat^T, M=16384, N=1536, K=1024 (split at 512)
        dim3 gg3(3*DD/128, ROWS/128, 1);   // (12, 128)
        gemm_mma<<<gg3, 256, GEMM_SMEM>>>(ainh, ainl, aouth, aoutl, DD, DD, 0,
                                          wcath, wcatl, 2*DD,
                                          gates, 3*DD,
                                          nullptr, nullptr, nullptr, nullptr, 0,
                                          2*DD, 0L, 0L, 0L, 0L);

        // u3 = nodes @ w3u^T, M=16384, N=512, K=512
        dim3 gg(DD/128, ROWS/128, 1);
        gemm_mma<<<gg, 256, GEMM_SMEM>>>(ndbh, ndbl, ndbh, ndbl, BIG, DD, 0,
                                         w3uh, w3ul, DD,
                                         u3, DD,
                                         nullptr, nullptr, nullptr, nullptr, 0,
                                         DD, 0L, 0L, 0L, 0L);

        elem1<<<ROWS*DD/2/256, 256>>>(b3w, b3u, b4w);

        // t = (rv*f) @ w5u^T
        gemm_mma<<<gg, 256, GEMM_SMEM>>>(rfh, rfl, rfh, rfl, BIG, DD, 0,
                                         w5uh, w5ul, DD,
                                         tt, DD,
                                         nullptr, nullptr, nullptr, nullptr, 0,
                                         DD, 0L, 0L, 0L, 0L);

        elem2<<<ROWS*DD/256, 256>>>(b5w, b5u);
    }

    copy4<<<(BB*NN*DD/4 + 255)/256, 256>>>((const float4*)nodes, (float4*)out, BB*NN*DD/4);
    copy4<<<(NN*NN/4 + 255)/256, 256>>>((const float4*)in_m,
                                        (float4*)(out + (long)BB*NN*DD), NN*NN/4);
}

// round 7
// speedup vs baseline: 1.9869x; 1.0161x over previous
#include <cuda_runtime.h>
#include <cuda_bf16.h>
#include <cstdint>
#include <math.h>

#define BB 16
#define NN 1024
#define DD 512
#define ROWS (BB*NN)          // 16384
#define TIME_STEP 3

// ---------------- fp32 scratch ----------------
__device__ float g_nodes[BB*NN*DD];
__device__ float g_u3   [BB*NN*DD];          // u3, then zv
__device__ float g_t    [BB*NN*DD];          // (rv*f)@w5u^T
__device__ float g_gates[BB*NN*3*DD];        // [16384][1536]

// ---------------- bf16 hi/lo operand buffers ----------------
__device__ __nv_bfloat16 g_inM_h [NN*NN], g_inM_l [NN*NN];
__device__ __nv_bfloat16 g_outM_h[NN*NN], g_outM_l[NN*NN];
__device__ __nv_bfloat16 g_wcat_h[3*DD*2*DD], g_wcat_l[3*DD*2*DD];  // [1536][1024]
__device__ __nv_bfloat16 g_w3u_h[DD*DD],   g_w3u_l[DD*DD];
__device__ __nv_bfloat16 g_w5u_h[DD*DD],   g_w5u_l[DD*DD];
__device__ __nv_bfloat16 g_ndT_h[BB*DD*NN], g_ndT_l[BB*DD*NN];   // [b][d][n]
__device__ __nv_bfloat16 g_ndb_h[BB*NN*DD], g_ndb_l[BB*NN*DD];   // [b][n][d]
__device__ __nv_bfloat16 g_ain_h[BB*NN*DD], g_ain_l[BB*NN*DD];
__device__ __nv_bfloat16 g_aout_h[BB*NN*DD], g_aout_l[BB*NN*DD];
__device__ __nv_bfloat16 g_rf_h [BB*NN*DD], g_rf_l [BB*NN*DD];

// ---------------- helpers ----------------
__device__ __forceinline__ uint32_t smem_u32(const void* p) {
    uint32_t a;
    asm("{ .reg .u64 t; cvta.to.shared.u64 t, %1; cvt.u32.u64 %0, t; }" : "=r"(a) : "l"(p));
    return a;
}
__device__ __forceinline__ void split2(float x, float y, uint32_t& hi, uint32_t& lo) {
    __nv_bfloat162 h = __floats2bfloat162_rn(x, y);   // low=x, high=y
    float rx = x - __bfloat162float(__low2bfloat16(h));
    float ry = y - __bfloat162float(__high2bfloat16(h));
    __nv_bfloat162 l = __floats2bfloat162_rn(rx, ry);
    hi = *(uint32_t*)&h; lo = *(uint32_t*)&l;
}
__device__ __forceinline__ void cpa16(uint32_t s, const void* g) {
    asm volatile("cp.async.cg.shared.global [%0], [%1], 16;" :: "r"(s), "l"(g));
}
__device__ __forceinline__ void cpa_commit() {
    asm volatile("cp.async.commit_group;" ::: "memory");
}
__device__ __forceinline__ void cpa_wait2() {
    asm volatile("cp.async.wait_group 2;" ::: "memory");
}
__device__ __forceinline__ void ldm_x4(uint32_t* r, uint32_t addr) {
    asm volatile("ldmatrix.sync.aligned.m8n8.x4.shared.b16 {%0,%1,%2,%3}, [%4];"
                 : "=r"(r[0]), "=r"(r[1]), "=r"(r[2]), "=r"(r[3]) : "r"(addr));
}
__device__ __forceinline__ void mma_bf16(float* d, const uint32_t* a, const uint32_t* b) {
    asm volatile("mma.sync.aligned.m16n8k16.row.col.f32.bf16.bf16.f32 "
                 "{%0,%1,%2,%3}, {%4,%5,%6,%7}, {%8,%9}, {%0,%1,%2,%3};"
                 : "+f"(d[0]), "+f"(d[1]), "+f"(d[2]), "+f"(d[3])
                 : "r"(a[0]), "r"(a[1]), "r"(a[2]), "r"(a[3]), "r"(b[0]), "r"(b[1]));
}

// ======================= bf16x3 mma.sync GEMM (512 threads) =======================
// C[m][n] = sum_k A'[m][k]*B[n][k]; A,B pre-split bf16 hi/lo, k-major.
// msel=0: A' = A for k<ksplit else A2 at k-ksplit; batch z via aB/bB/cB/coB.
// msel=1: matrix pair (A vs A2) chosen by z>=16; batch = z&15; epilogue goes
//         to (Coh,Col) for z<16 and (Co2h,Co2l) for z>=16. ksplit unused.
#define KC 32
#define RS 40                      // smem row stride in halves (80B, conflict-free)
#define TILE_HB (128*RS)           // halves per tile
#define STAGE_HB (4*TILE_HB)       // Ahi|Alo|Bhi|Blo
#define NSTAGE 4
#define GEMM_SMEM (NSTAGE*STAGE_HB*2)   // 163840 bytes
#define NT 512

__device__ __forceinline__ void load_tile(uint32_t sbase, const __nv_bfloat16* g,
                                          int ld, int tid)
{
    int row = tid >> 2, cb = tid & 3;      // 512 threads: one 16B op per tile
    cpa16(sbase + (uint32_t)(row*RS + cb*8)*2, g + (long)row*ld + cb*8);
}

__global__ __launch_bounds__(NT, 1)
void gemm_mma(const __nv_bfloat16* __restrict__ Ah, const __nv_bfloat16* __restrict__ Al,
              const __nv_bfloat16* __restrict__ A2h, const __nv_bfloat16* __restrict__ A2l,
              int ksplit, int lda, int msel,
              const __nv_bfloat16* __restrict__ Bh, const __nv_bfloat16* __restrict__ Bl,
              int ldb,
              float* __restrict__ C, int ldc,
              __nv_bfloat16* __restrict__ Coh, __nv_bfloat16* __restrict__ Col,
              __nv_bfloat16* __restrict__ Co2h, __nv_bfloat16* __restrict__ Co2l,
              int ldco,
              int Kd, long aB, long bB, long cB, long coB)
{
    extern __shared__ char smem[];
    const uint32_t sb = smem_u32(smem);

    long z = blockIdx.z;
    if (msel) {
        if (z >= 16) { Ah = A2h; Al = A2l; Coh = Co2h; Col = Co2l; z -= 16; }
        A2h = Ah; A2l = Al;
        ksplit = 1 << 30;
    }
    Ah += z*aB; Al += z*aB; A2h += z*aB; A2l += z*aB;
    Bh += z*bB; Bl += z*bB;
    if (C)   C   += z*cB;
    if (Coh) { Coh += z*coB; Col += z*coB; }

    const int tid = threadIdx.x;
    const int wid = tid >> 5, lane = tid & 31;
    const int m0 = blockIdx.y * 128, n0 = blockIdx.x * 128;
    const int wrow = (wid & 3) * 32;       // 4 warp-rows
    const int wcol = (wid >> 2) * 32;      // 4 warp-cols

    float acc[2][4][4];
    #pragma unroll
    for (int i = 0; i < 2; i++)
        #pragma unroll
        for (int j = 0; j < 4; j++)
            #pragma unroll
            for (int k = 0; k < 4; k++) acc[i][j][k] = 0.f;

    const int KT = Kd / KC;

    auto load_stage = [&](int t) {
        int kbase = t * KC;
        const __nv_bfloat16 *pah = Ah, *pal = Al;
        int ka = kbase;
        if (kbase >= ksplit) { pah = A2h; pal = A2l; ka -= ksplit; }
        uint32_t s = sb + (uint32_t)(t % NSTAGE) * STAGE_HB * 2;
        load_tile(s,               pah + (long)m0*lda + ka,    lda, tid);
        load_tile(s + TILE_HB*2,   pal + (long)m0*lda + ka,    lda, tid);
        load_tile(s + 2*TILE_HB*2, Bh  + (long)n0*ldb + kbase, ldb, tid);
        load_tile(s + 3*TILE_HB*2, Bl  + (long)n0*ldb + kbase, ldb, tid);
    };

    load_stage(0); cpa_commit();
    load_stage(1); cpa_commit();
    load_stage(2); cpa_commit();

    const int ar = lane & 15, acg = lane >> 4;
    const int bg = lane >> 3, bl8 = lane & 7;

    for (int t = 0; t < KT; t++) {
        cpa_wait2();          // stage t complete (<=2 newer groups pending)
        __syncthreads();      // publish stage t; all warps done with stage t-1
        if (t + 3 < KT) load_stage(t + 3);   // overwrites buffer (t-1)%4: safe
        cpa_commit();         // keep group accounting uniform

        const uint32_t s = sb + (uint32_t)(t % NSTAGE) * STAGE_HB * 2;
        const uint32_t sAh = s, sAl = s + TILE_HB*2;
        const uint32_t sBh = s + 2*TILE_HB*2, sBl = s + 3*TILE_HB*2;

        #pragma unroll
        for (int ks = 0; ks < 2; ks++) {
            uint32_t ah[2][4], al[2][4], bh[2][4], bl[2][4];
            #pragma unroll
            for (int mb = 0; mb < 2; mb++) {
                uint32_t off = (uint32_t)((wrow + mb*16 + ar)*RS + ks*16 + acg*8)*2;
                ldm_x4(ah[mb], sAh + off);
                ldm_x4(al[mb], sAl + off);
            }
            #pragma unroll
            for (int nb2 = 0; nb2 < 2; nb2++) {
                int rowb = wcol + nb2*16 + ((bg >> 1) & 1)*8 + bl8;
                int kcb  = ks*16 + (bg & 1)*8;
                uint32_t off = (uint32_t)(rowb*RS + kcb)*2;
                ldm_x4(bh[nb2], sBh + off);
                ldm_x4(bl[nb2], sBl + off);
            }
            #pragma unroll
            for (int mb = 0; mb < 2; mb++)
                #pragma unroll
                for (int nb = 0; nb < 4; nb++) {
                    const uint32_t* ph = &bh[nb >> 1][(nb & 1)*2];
                    const uint32_t* pl = &bl[nb >> 1][(nb & 1)*2];
                    mma_bf16(acc[mb][nb], ah[mb], ph);
                    mma_bf16(acc[mb][nb], ah[mb], pl);
                    mma_bf16(acc[mb][nb], al[mb], ph);
                }
        }
    }

    // ---- epilogue ----
    const int r0 = lane >> 2, c0 = (lane & 3)*2;
    #pragma unroll
    for (int mb = 0; mb < 2; mb++) {
        #pragma unroll
        for (int nb = 0; nb < 4; nb++) {
            long row = m0 + wrow + mb*16 + r0;
            int  col = n0 + wcol + nb*8 + c0;
            float* a = acc[mb][nb];
            if (C) {
                *(float2*)&C[row*ldc + col]     = make_float2(a[0], a[1]);
                *(float2*)&C[(row+8)*ldc + col] = make_float2(a[2], a[3]);
            }
            if (Coh) {
                uint32_t hi, lo;
                split2(a[0], a[1], hi, lo);
                *(uint32_t*)&Coh[row*ldco + col] = hi;
                *(uint32_t*)&Col[row*ldco + col] = lo;
                split2(a[2], a[3], hi, lo);
                *(uint32_t*)&Coh[(row+8)*ldco + col] = hi;
                *(uint32_t*)&Col[(row+8)*ldco + col] = lo;
            }
        }
    }
}

// ---------------- fused one-time converter ----------------
__global__ void cvt_all(const float* __restrict__ in_m, const float* __restrict__ out_m,
                        const float* __restrict__ w3w, const float* __restrict__ w4w,
                        const float* __restrict__ w5w, const float* __restrict__ w3u,
                        const float* __restrict__ w5u)
{
    long p = ((long)blockIdx.x*blockDim.x + threadIdx.x) * 2;
    const long S0 = 1048576, S1 = 2097152, S2 = S1 + 524288, S3 = S2 + 524288,
               S4 = S3 + 524288, S5 = S4 + 262144, S6 = S5 + 262144;
    if (p >= S6) return;
    const float* src; __nv_bfloat16 *dh, *dl; long off;
    if      (p < S0) { src = in_m;  dh = g_inM_h;  dl = g_inM_l;  off = p; }
    else if (p < S1) { src = out_m; dh = g_outM_h; dl = g_outM_l; off = p - S0; }
    else if (p < S2) { src = w3w; dh = g_wcat_h;           dl = g_wcat_l;           off = p - S1; }
    else if (p < S3) { src = w4w; dh = g_wcat_h + 524288;  dl = g_wcat_l + 524288;  off = p - S2; }
    else if (p < S4) { src = w5w; dh = g_wcat_h + 1048576; dl = g_wcat_l + 1048576; off = p - S3; }
    else if (p < S5) { src = w3u; dh = g_w3u_h; dl = g_w3u_l; off = p - S4; }
    else             { src = w5u; dh = g_w5u_h; dl = g_w5u_l; off = p - S5; }
    float2 v = *(const float2*)&src[off];
    uint32_t h, l;
    split2(v.x, v.y, h, l);
    *(uint32_t*)&dh[off] = h;
    *(uint32_t*)&dl[off] = l;
}

// nodes [b][n][d] fp32 -> ndb hi/lo (straight) + ndT hi/lo (transposed [b][d][n])
__global__ void transpose_cvt(const float* __restrict__ src)
{
    __shared__ float tile[32][33];
    const int b = blockIdx.z;
    const int d0 = blockIdx.x*32, n0 = blockIdx.y*32;
    const float* s = src + (long)b*NN*DD;
    const int tid = threadIdx.x;
    #pragma unroll
    for (int i = 0; i < 4; i++) {
        int p = tid + i*256, n = p >> 5, d = p & 31;
        tile[n][d] = s[(long)(n0+n)*DD + d0 + d];
    }
    __syncthreads();
    #pragma unroll
    for (int i = 0; i < 2; i++) {
        int p = tid + i*256, n = p >> 4, dp = p & 15;
        uint32_t h, l;
        split2(tile[n][dp*2], tile[n][dp*2+1], h, l);
        long o = ((long)b*NN + n0 + n)*DD + d0 + dp*2;
        *(uint32_t*)&g_ndb_h[o] = h; *(uint32_t*)&g_ndb_l[o] = l;
    }
    #pragma unroll
    for (int i = 0; i < 2; i++) {
        int p = tid + i*256, d = p >> 4, np = p & 15;
        uint32_t h, l;
        split2(tile[np*2][d], tile[np*2+1][d], h, l);
        long o = ((long)b*DD + d0 + d)*NN + n0 + np*2;
        *(uint32_t*)&g_ndT_h[o] = h; *(uint32_t*)&g_ndT_l[o] = l;
    }
}

// ---------------- elementwise ----------------
__global__ void elem1(const float* __restrict__ b3w, const float* __restrict__ b3u,
                      const float* __restrict__ b4w)
{
    int p = blockIdx.x*blockDim.x + threadIdx.x;
    long i = (long)p*2;
    int row = (int)(i >> 9), e = (int)(i & 511);
    float2 u = *(const float2*)&g_u3[i];
    float2 f = *(const float2*)&g_nodes[i];
    float g3a = g_gates[(long)row*1536 + e],       g3b = g_gates[(long)row*1536 + e + 1];
    float g4a = g_gates[(long)row*1536 + 512 + e], g4b = g_gates[(long)row*1536 + 512 + e + 1];
    float ua = u.x + b3u[e], ub = u.y + b3u[e+1];
    float za = 1.f/(1.f + expf(-(g3a + b3w[e] + ua)));
    float zb = 1.f/(1.f + expf(-(g3b + b3w[e+1] + ub)));
    float ra = 1.f/(1.f + expf(-(g4a + b4w[e] + ua)));
    float rb = 1.f/(1.f + expf(-(g4b + b4w[e+1] + ub)));
    *(float2*)&g_u3[i] = make_float2(za, zb);
    uint32_t h, l;
    split2(ra*f.x, rb*f.y, h, l);
    *(uint32_t*)&g_rf_h[i] = h;
    *(uint32_t*)&g_rf_l[i] = l;
}

__global__ void elem2(const float* __restrict__ b5w, const float* __restrict__ b5u)
{
    long i = (long)blockIdx.x*blockDim.x + threadIdx.x;
    int row = (int)(i >> 9), e = (int)(i & 511);
    float t  = g_t[i];
    float g5 = g_gates[(long)row*1536 + 1024 + e];
    float hv = tanhf(g5 + b5w[e] + t + b5u[e]);
    float z  = g_u3[i];
    float f  = g_nodes[i];
    g_nodes[i] = (1.f - z)*f + z*hv;
}

__global__ void copy4(const float4* __restrict__ src, float4* __restrict__ dst, int n4)
{
    int i = blockIdx.x*blockDim.x + threadIdx.x;
    if (i < n4) dst[i] = src[i];
}

// ---------------- host launcher ----------------
extern "C" void kernel_launch(void* const* d_in, const int* in_sizes, int n_in,
                              void* d_out, int out_size)
{
    (void)in_sizes; (void)n_in; (void)out_size;
    const float* x     = (const float*)d_in[0];
    const float* in_m  = (const float*)d_in[1];
    const float* out_m = (const float*)d_in[2];
    const float* w3w   = (const float*)d_in[3];
    const float* b3w   = (const float*)d_in[4];
    const float* w3u   = (const float*)d_in[5];
    const float* b3u   = (const float*)d_in[6];
    const float* w4w   = (const float*)d_in[7];
    const float* b4w   = (const float*)d_in[8];
    const float* w5w   = (const float*)d_in[9];
    const float* b5w   = (const float*)d_in[10];
    const float* w5u   = (const float*)d_in[11];
    const float* b5u   = (const float*)d_in[12];
    float* out = (float*)d_out;

    float *nodes, *u3, *tt, *gates;
    cudaGetSymbolAddress((void**)&nodes, g_nodes);
    cudaGetSymbolAddress((void**)&u3,    g_u3);
    cudaGetSymbolAddress((void**)&tt,    g_t);
    cudaGetSymbolAddress((void**)&gates, g_gates);

    __nv_bfloat16 *inMh,*inMl,*outMh,*outMl,*wcath,*wcatl;
    __nv_bfloat16 *w3uh,*w3ul,*w5uh,*w5ul,*ndTh,*ndTl,*ndbh,*ndbl;
    __nv_bfloat16 *ainh,*ainl,*aouth,*aoutl,*rfh,*rfl;
    cudaGetSymbolAddress((void**)&inMh, g_inM_h);  cudaGetSymbolAddress((void**)&inMl, g_inM_l);
    cudaGetSymbolAddress((void**)&outMh,g_outM_h); cudaGetSymbolAddress((void**)&outMl,g_outM_l);
    cudaGetSymbolAddress((void**)&wcath,g_wcat_h); cudaGetSymbolAddress((void**)&wcatl,g_wcat_l);
    cudaGetSymbolAddress((void**)&w3uh, g_w3u_h);  cudaGetSymbolAddress((void**)&w3ul, g_w3u_l);
    cudaGetSymbolAddress((void**)&w5uh, g_w5u_h);  cudaGetSymbolAddress((void**)&w5ul, g_w5u_l);
    cudaGetSymbolAddress((void**)&ndTh, g_ndT_h);  cudaGetSymbolAddress((void**)&ndTl, g_ndT_l);
    cudaGetSymbolAddress((void**)&ndbh, g_ndb_h);  cudaGetSymbolAddress((void**)&ndbl, g_ndb_l);
    cudaGetSymbolAddress((void**)&ainh, g_ain_h);  cudaGetSymbolAddress((void**)&ainl, g_ain_l);
    cudaGetSymbolAddress((void**)&aouth,g_aout_h); cudaGetSymbolAddress((void**)&aoutl,g_aout_l);
    cudaGetSymbolAddress((void**)&rfh,  g_rf_h);   cudaGetSymbolAddress((void**)&rfl,  g_rf_l);

    cudaFuncSetAttribute(gemm_mma, cudaFuncAttributeMaxDynamicSharedMemorySize, GEMM_SMEM);

    const long ND = (long)NN*DD;     // 524288
    const int  BIG = 1 << 30;

    copy4<<<(BB*NN*DD/4 + 255)/256, 256>>>((const float4*)x, (float4*)nodes, BB*NN*DD/4);
    cvt_all<<<8192, 256>>>(in_m, out_m, w3w, w4w, w5w, w3u, w5u);

    for (int step = 0; step < TIME_STEP; step++) {
        transpose_cvt<<<dim3(DD/32, NN/32, BB), 256>>>(nodes);

        // fused a_in + a_out: M=1024, N=512, K=1024, z=0..31 (z>=16 -> out_matrix)
        dim3 gp(DD/128, NN/128, 2*BB);
        gemm_mma<<<gp, NT, GEMM_SMEM>>>(inMh, inMl, outMh, outMl, BIG, NN, 1,
                                        ndTh, ndTl, NN,
                                        nullptr, 0,
                                        ainh, ainl, aouth, aoutl, DD,
                                        NN, 0L, ND, 0L, ND);

        // fused gates: [ain|aout] @ wcat^T, M=16384, N=1536, K=1024 (split at 512)
        dim3 gg3(3*DD/128, ROWS/128, 1);   // (12, 128)
        gemm_mma<<<gg3, NT, GEMM_SMEM>>>(ainh, ainl, aouth, aoutl, DD, DD, 0,
                                         wcath, wcatl, 2*DD,
                                         gates, 3*DD,
                                         nullptr, nullptr, nullptr, nullptr, 0,
                                         2*DD, 0L, 0L, 0L, 0L);

        // u3 = nodes @ w3u^T, M=16384, N=512, K=512
        dim3 gg(DD/128, ROWS/128, 1);
        gemm_mma<<<gg, NT, GEMM_SMEM>>>(ndbh, ndbl, ndbh, ndbl, BIG, DD, 0,
                                        w3uh, w3ul, DD,
                                        u3, DD,
                                        nullptr, nullptr, nullptr, nullptr, 0,
                                        DD, 0L, 0L, 0L, 0L);

        elem1<<<ROWS*DD/2/256, 256>>>(b3w, b3u, b4w);

        // t = (rv*f) @ w5u^T
        gemm_mma<<<gg, NT, GEMM_SMEM>>>(rfh, rfl, rfh, rfl, BIG, DD, 0,
                                        w5uh, w5ul, DD,
                                        tt, DD,
                                        nullptr, nullptr, nullptr, nullptr, 0,
                                        DD, 0L, 0L, 0L, 0L);

        elem2<<<ROWS*DD/256, 256>>>(b5w, b5u);
    }

    copy4<<<(BB*NN*DD/4 + 255)/256, 256>>>((const float4*)nodes, (float4*)out, BB*NN*DD/4);
    copy4<<<(NN*NN/4 + 255)/256, 256>>>((const float4*)in_m,
                                        (float4*)(out + (long)BB*NN*DD), NN*NN/4);
}